// round 9
// baseline (speedup 1.0000x reference)
#include <cuda_runtime.h>
#include <cstdint>

#define N_MAX 50000
#define E_MAX 800000
#define C 64
#define FIN 128
#define D 192
#define NEG_SLOPE 0.2f
#define SCAN_B 512

// ---------------- scratch (static __device__; no allocations allowed) -------
__device__ __align__(16) float g_hzr[N_MAX * 128];   // interleaved z/r: [z2p,z2p+1,r2p,r2p+1]
__device__ __align__(16) float g_hh[N_MAX * C];
__device__ __align__(16) float g_Z[N_MAX * C];
__device__ __align__(16) float g_HR[N_MAX * C];
__device__ float g_als_z[N_MAX], g_ald_z[N_MAX];
__device__ float g_als_r[N_MAX], g_ald_r[N_MAX];
__device__ float g_als_h[N_MAX], g_ald_h[N_MAX];
__device__ int g_cnt[N_MAX];
__device__ int g_rs[N_MAX + 1];     // CSR row starts (by dst)
__device__ int g_cur[N_MAX];        // scatter cursors
__device__ int g_bsum[512], g_boff[512];
__device__ int g_csrc[E_MAX];       // src node per CSR slot

// ---------------- helpers ----------------
__device__ __forceinline__ float lrelu(float x) { return x > 0.f ? x : NEG_SLOPE * x; }
__device__ __forceinline__ float sigmoidf_(float x) { return 1.f / (1.f + __expf(-x)); }

// ================= CSR build =================
__global__ void k_zero_cnt(int n) {
    int i = blockIdx.x * blockDim.x + threadIdx.x;
    if (i < n) g_cnt[i] = 0;
}
__global__ void k_count(const int* __restrict__ dst, int E) {
    int e = blockIdx.x * blockDim.x + threadIdx.x;
    if (e < E) atomicAdd(&g_cnt[dst[e]], 1);
}
__global__ void k_scan1(int n) {   // block-chunk reduce -> g_bsum
    __shared__ int sm[SCAN_B];
    int i = blockIdx.x * SCAN_B + threadIdx.x;
    int c = (i < n) ? g_cnt[i] : 0;
    sm[threadIdx.x] = c;
    __syncthreads();
    for (int off = SCAN_B / 2; off; off >>= 1) {
        if (threadIdx.x < off) sm[threadIdx.x] += sm[threadIdx.x + off];
        __syncthreads();
    }
    if (threadIdx.x == 0) g_bsum[blockIdx.x] = sm[0];
}
__global__ void k_scan2(int nb, int n) {  // parallel scan of block sums (one block)
    __shared__ int sm[512];
    int t = threadIdx.x;
    int v = (t < nb) ? g_bsum[t] : 0;
    sm[t] = v;
    __syncthreads();
    for (int off = 1; off < 512; off <<= 1) {
        int u = (t >= off) ? sm[t - off] : 0;
        __syncthreads();
        sm[t] += u;
        __syncthreads();
    }
    if (t < nb) g_boff[t] = sm[t] - v;   // exclusive
    if (t == 511) g_rs[n] = sm[511];
}
__global__ void k_scan3(int n) {   // per-chunk exclusive scan + offset
    __shared__ int sm[SCAN_B];
    int t = threadIdx.x;
    int i = blockIdx.x * SCAN_B + t;
    int c = (i < n) ? g_cnt[i] : 0;
    sm[t] = c;
    __syncthreads();
    for (int off = 1; off < SCAN_B; off <<= 1) {
        int v = (t >= off) ? sm[t - off] : 0;
        __syncthreads();
        sm[t] += v;
        __syncthreads();
    }
    if (i < n) {
        int excl = g_boff[blockIdx.x] + sm[t] - c;
        g_rs[i] = excl;
        g_cur[i] = excl;
    }
}
__global__ void k_scatter(const int* __restrict__ src, const int* __restrict__ dst, int E) {
    int e = blockIdx.x * blockDim.x + threadIdx.x;
    if (e < E) {
        int pos = atomicAdd(&g_cur[dst[e]], 1);
        g_csrc[pos] = src[e];
    }
}

// ================= GEMMs: 8x8 register-blocked fp32 SIMT =================
// O = [A1 | A2] (n x 192) @ B (192 x 64) per gate.
// gemm_zr: BM=128, BN=128 physical (z|r interleaved in pairs), 256 thr (16x16),
// 8x8 per thread. B tile is assembled in smem directly in the interleaved
// output layout: physical col 4p+{0,1} = Wz col 2p+{0,1}; 4p+{2,3} = Wr.
__global__ void __launch_bounds__(256)
gemm_zr(const float* __restrict__ A1, const float* __restrict__ A2,
        const float* __restrict__ B1, const float* __restrict__ B2, int n)
{
    __shared__ float As[16 * 128];   // [k][m]
    __shared__ float Bs[16 * 128];   // [k][physical col]

    int tid = threadIdx.x;
    int row0 = blockIdx.x * 128;
    int tr = tid >> 4;               // 0..15 (8 rows each)
    int tc = tid & 15;               // 0..15 (8 physical cols each)

    float acc[8][8];
#pragma unroll
    for (int i = 0; i < 8; i++)
#pragma unroll
        for (int j = 0; j < 8; j++) acc[i][j] = 0.f;

    int a_row = tid >> 1;            // 0..127
    int a_kg = (tid & 1) * 8;        // 0 or 8
    int b_kk = tid >> 4;             // 0..15
    int b_q = tid & 15;              // pair-group: physical cols 8q..8q+7

    for (int k0 = 0; k0 < D; k0 += 16) {
        // --- A tile (128 x 16) -> As[k][m] ---
        {
            int grow = row0 + a_row;
#pragma unroll
            for (int h = 0; h < 2; h++) {
                int k = k0 + a_kg + h * 4;
                float4 v = make_float4(0.f, 0.f, 0.f, 0.f);
                if (grow < n) {
                    if (k < FIN) v = *(const float4*)(A1 + (size_t)grow * FIN + k);
                    else         v = *(const float4*)(A2 + (size_t)grow * C + (k - FIN));
                }
                int kk = a_kg + h * 4;
                As[(kk + 0) * 128 + a_row] = v.x;
                As[(kk + 1) * 128 + a_row] = v.y;
                As[(kk + 2) * 128 + a_row] = v.z;
                As[(kk + 3) * 128 + a_row] = v.w;
            }
        }
        // --- B tile (16 x 128 physical): interleave Wz/Wr pairs ---
        {
            // physical cols 8q..8q+7 = {z[4q],z[4q+1],r[4q],r[4q+1],z[4q+2],z[4q+3],r[4q+2],r[4q+3]}
            float4 vz = *(const float4*)(B1 + (size_t)(k0 + b_kk) * C + b_q * 4);
            float4 vr = *(const float4*)(B2 + (size_t)(k0 + b_kk) * C + b_q * 4);
            float* o = Bs + b_kk * 128 + b_q * 8;
            *(float4*)(o)     = make_float4(vz.x, vz.y, vr.x, vr.y);
            *(float4*)(o + 4) = make_float4(vz.z, vz.w, vr.z, vr.w);
        }
        __syncthreads();

#pragma unroll
        for (int kk = 0; kk < 16; kk++) {
            float4 a0 = *(const float4*)(As + kk * 128 + tr * 8);
            float4 a1 = *(const float4*)(As + kk * 128 + tr * 8 + 4);
            float av[8] = {a0.x, a0.y, a0.z, a0.w, a1.x, a1.y, a1.z, a1.w};
            float4 b0 = *(const float4*)(Bs + kk * 128 + tc * 8);
            float4 b1 = *(const float4*)(Bs + kk * 128 + tc * 8 + 4);
            float bv[8] = {b0.x, b0.y, b0.z, b0.w, b1.x, b1.y, b1.z, b1.w};
#pragma unroll
            for (int i = 0; i < 8; i++)
#pragma unroll
                for (int j = 0; j < 8; j++) acc[i][j] += av[i] * bv[j];
        }
        __syncthreads();
    }
    // store: 2 contiguous float4 per row (already interleaved layout)
#pragma unroll
    for (int i = 0; i < 8; i++) {
        int row = row0 + tr * 8 + i;
        if (row >= n) continue;
        float* o = g_hzr + (size_t)row * 128 + tc * 8;
        *(float4*)(o)     = make_float4(acc[i][0], acc[i][1], acc[i][2], acc[i][3]);
        *(float4*)(o + 4) = make_float4(acc[i][4], acc[i][5], acc[i][6], acc[i][7]);
    }
}

// gemm_h: BM=128, BN=64, 128 thr (16x8), 8x8 per thread, A2 = g_HR -> g_hh.
__global__ void __launch_bounds__(128)
gemm_h(const float* __restrict__ A1, const float* __restrict__ B1, int n)
{
    __shared__ float As[16 * 128];   // [k][m]
    __shared__ float Bs[16 * 64];    // [k][n]

    const float* A2 = g_HR;
    int tid = threadIdx.x;
    int row0 = blockIdx.x * 128;
    int tr = tid >> 3;               // 0..15
    int tc = tid & 7;                // 0..7

    float acc[8][8];
#pragma unroll
    for (int i = 0; i < 8; i++)
#pragma unroll
        for (int j = 0; j < 8; j++) acc[i][j] = 0.f;

    int b_kk = tid >> 3;             // 0..15
    int b_col = (tid & 7) * 8;       // 0..56

    for (int k0 = 0; k0 < D; k0 += 16) {
        // --- A tile (128 x 16): each thread 4 float4, row = tid ---
        {
            int grow = row0 + tid;
#pragma unroll
            for (int h = 0; h < 4; h++) {
                int k = k0 + h * 4;
                float4 v = make_float4(0.f, 0.f, 0.f, 0.f);
                if (grow < n) {
                    if (k < FIN) v = *(const float4*)(A1 + (size_t)grow * FIN + k);
                    else         v = *(const float4*)(A2 + (size_t)grow * C + (k - FIN));
                }
                int kk = h * 4;
                As[(kk + 0) * 128 + tid] = v.x;
                As[(kk + 1) * 128 + tid] = v.y;
                As[(kk + 2) * 128 + tid] = v.z;
                As[(kk + 3) * 128 + tid] = v.w;
            }
        }
        // --- B tile (16 x 64): each thread 2 float4 ---
        {
            float4 v0 = *(const float4*)(B1 + (size_t)(k0 + b_kk) * C + b_col);
            float4 v1 = *(const float4*)(B1 + (size_t)(k0 + b_kk) * C + b_col + 4);
            *(float4*)(Bs + b_kk * 64 + b_col)     = v0;
            *(float4*)(Bs + b_kk * 64 + b_col + 4) = v1;
        }
        __syncthreads();

#pragma unroll
        for (int kk = 0; kk < 16; kk++) {
            float4 a0 = *(const float4*)(As + kk * 128 + tr * 8);
            float4 a1 = *(const float4*)(As + kk * 128 + tr * 8 + 4);
            float av[8] = {a0.x, a0.y, a0.z, a0.w, a1.x, a1.y, a1.z, a1.w};
            float4 b0 = *(const float4*)(Bs + kk * 64 + tc * 8);
            float4 b1 = *(const float4*)(Bs + kk * 64 + tc * 8 + 4);
            float bv[8] = {b0.x, b0.y, b0.z, b0.w, b1.x, b1.y, b1.z, b1.w};
#pragma unroll
            for (int i = 0; i < 8; i++)
#pragma unroll
                for (int j = 0; j < 8; j++) acc[i][j] += av[i] * bv[j];
        }
        __syncthreads();
    }
#pragma unroll
    for (int i = 0; i < 8; i++) {
        int row = row0 + tr * 8 + i;
        if (row >= n) continue;
        float* o = g_hh + (size_t)row * C + tc * 8;
        *(float4*)(o)     = make_float4(acc[i][0], acc[i][1], acc[i][2], acc[i][3]);
        *(float4*)(o + 4) = make_float4(acc[i][4], acc[i][5], acc[i][6], acc[i][7]);
    }
}

// ================= attention scalars =================
// z & r fused from interleaved layout. warp per node.
__global__ void node_attn_zr(const float* __restrict__ az_s, const float* __restrict__ az_d,
                             const float* __restrict__ ar_s, const float* __restrict__ ar_d,
                             int n)
{
    int w = (blockIdx.x * blockDim.x + threadIdx.x) >> 5;
    if (w >= n) return;
    int l = threadIdx.x & 31;
    float4 v = *(const float4*)(g_hzr + (size_t)w * 128 + 4 * l);
    float c0s = __ldg(az_s + 2 * l), c1s = __ldg(az_s + 2 * l + 1);
    float c0d = __ldg(az_d + 2 * l), c1d = __ldg(az_d + 2 * l + 1);
    float r0s = __ldg(ar_s + 2 * l), r1s = __ldg(ar_s + 2 * l + 1);
    float r0d = __ldg(ar_d + 2 * l), r1d = __ldg(ar_d + 2 * l + 1);
    float sz = v.x * c0s + v.y * c1s;
    float dz = v.x * c0d + v.y * c1d;
    float sr = v.z * r0s + v.w * r1s;
    float dr = v.z * r0d + v.w * r1d;
#pragma unroll
    for (int o = 16; o; o >>= 1) {
        sz += __shfl_xor_sync(0xffffffffu, sz, o);
        dz += __shfl_xor_sync(0xffffffffu, dz, o);
        sr += __shfl_xor_sync(0xffffffffu, sr, o);
        dr += __shfl_xor_sync(0xffffffffu, dr, o);
    }
    if (l == 0) { g_als_z[w] = sz; g_ald_z[w] = dz; g_als_r[w] = sr; g_ald_r[w] = dr; }
}

__global__ void node_attn_h(const float* __restrict__ a_src, const float* __restrict__ a_dst, int n)
{
    int w = (blockIdx.x * blockDim.x + threadIdx.x) >> 5;
    if (w >= n) return;
    int l = threadIdx.x & 31;
    float h0 = g_hh[(size_t)w * C + l];
    float h1 = g_hh[(size_t)w * C + 32 + l];
    float s = h0 * __ldg(a_src + l) + h1 * __ldg(a_src + 32 + l);
    float d = h0 * __ldg(a_dst + l) + h1 * __ldg(a_dst + 32 + l);
#pragma unroll
    for (int o = 16; o; o >>= 1) {
        s += __shfl_xor_sync(0xffffffffu, s, o);
        d += __shfl_xor_sync(0xffffffffu, d, o);
    }
    if (l == 0) { g_als_h[w] = s; g_ald_h[w] = d; }
}

// ================= fused per-dst accumulation =================
// z & r gates: warp per dst node, register accumulators, unroll-by-2.
__global__ void zr_node(const float* __restrict__ H,
                        const float* __restrict__ bz, const float* __restrict__ br, int n)
{
    int d = (blockIdx.x * blockDim.x + threadIdx.x) >> 5;
    if (d >= n) return;
    int l = threadIdx.x & 31;

    float aldz = g_ald_z[d], aldr = g_ald_r[d];
    float alsz = g_als_z[d], alsr = g_als_r[d];

    float ez = 0.f, er = 0.f;
    if (l == 0)  ez = __expf(lrelu(alsz + aldz));
    if (l == 16) er = __expf(lrelu(alsr + aldr));
    ez = __shfl_sync(0xffffffffu, ez, 0);
    er = __shfl_sync(0xffffffffu, er, 16);

    float4 v = *(const float4*)(g_hzr + (size_t)d * 128 + 4 * l);
    float az0 = v.x * ez, az1 = v.y * ez;
    float ar0 = v.z * er, ar1 = v.w * er;
    float denz = ez, denr = er;

    int b = g_rs[d], e_end = g_rs[d + 1];
    int i = b;
    for (; i + 1 < e_end; i += 2) {
        int s0 = g_csrc[i], s1 = g_csrc[i + 1];
        float t0 = 0.f, t1 = 0.f;
        if (l == 0)  t0 = __expf(lrelu(g_als_z[s0] + aldz));
        if (l == 1)  t1 = __expf(lrelu(g_als_z[s1] + aldz));
        if (l == 16) t0 = __expf(lrelu(g_als_r[s0] + aldr));
        if (l == 17) t1 = __expf(lrelu(g_als_r[s1] + aldr));
        float ez0 = __shfl_sync(0xffffffffu, t0, 0);
        float ez1 = __shfl_sync(0xffffffffu, t1, 1);
        float er0 = __shfl_sync(0xffffffffu, t0, 16);
        float er1 = __shfl_sync(0xffffffffu, t1, 17);
        float4 u0 = *(const float4*)(g_hzr + (size_t)s0 * 128 + 4 * l);
        float4 u1 = *(const float4*)(g_hzr + (size_t)s1 * 128 + 4 * l);
        az0 += u0.x * ez0 + u1.x * ez1;
        az1 += u0.y * ez0 + u1.y * ez1;
        ar0 += u0.z * er0 + u1.z * er1;
        ar1 += u0.w * er0 + u1.w * er1;
        denz += ez0 + ez1;
        denr += er0 + er1;
    }
    if (i < e_end) {
        int s0 = g_csrc[i];
        float t0 = 0.f;
        if (l == 0)  t0 = __expf(lrelu(g_als_z[s0] + aldz));
        if (l == 16) t0 = __expf(lrelu(g_als_r[s0] + aldr));
        float ez0 = __shfl_sync(0xffffffffu, t0, 0);
        float er0 = __shfl_sync(0xffffffffu, t0, 16);
        float4 u0 = *(const float4*)(g_hzr + (size_t)s0 * 128 + 4 * l);
        az0 += u0.x * ez0; az1 += u0.y * ez0;
        ar0 += u0.z * er0; ar1 += u0.w * er0;
        denz += ez0; denr += er0;
    }

    float iz = 1.f / (denz + 1e-16f), ir = 1.f / (denr + 1e-16f);
    float Z0 = sigmoidf_(az0 * iz + __ldg(bz + 2 * l));
    float Z1 = sigmoidf_(az1 * iz + __ldg(bz + 2 * l + 1));
    float R0 = sigmoidf_(ar0 * ir + __ldg(br + 2 * l));
    float R1 = sigmoidf_(ar1 * ir + __ldg(br + 2 * l + 1));
    float2 Hv = *(const float2*)(H + (size_t)d * C + 2 * l);
    *(float2*)(g_Z  + (size_t)d * C + 2 * l) = make_float2(Z0, Z1);
    *(float2*)(g_HR + (size_t)d * C + 2 * l) = make_float2(Hv.x * R0, Hv.y * R1);
}

// h gate: warp per dst node; tanh + GRU combine fused; writes final output.
__global__ void h_node(const float* __restrict__ H, const float* __restrict__ bh,
                       float* __restrict__ out, int n)
{
    int d = (blockIdx.x * blockDim.x + threadIdx.x) >> 5;
    if (d >= n) return;
    int l = threadIdx.x & 31;

    float aldh = g_ald_h[d];
    float alsh = g_als_h[d];

    float eh = 0.f;
    if (l == 0) eh = __expf(lrelu(alsh + aldh));
    eh = __shfl_sync(0xffffffffu, eh, 0);

    float2 v = *(const float2*)(g_hh + (size_t)d * C + 2 * l);
    float a0 = v.x * eh, a1 = v.y * eh;
    float den = eh;

    int b = g_rs[d], e_end = g_rs[d + 1];
    int i = b;
    for (; i + 1 < e_end; i += 2) {
        int s0 = g_csrc[i], s1 = g_csrc[i + 1];
        float t0 = 0.f, t1 = 0.f;
        if (l == 0) t0 = __expf(lrelu(g_als_h[s0] + aldh));
        if (l == 1) t1 = __expf(lrelu(g_als_h[s1] + aldh));
        float eh0 = __shfl_sync(0xffffffffu, t0, 0);
        float eh1 = __shfl_sync(0xffffffffu, t1, 1);
        float2 u0 = *(const float2*)(g_hh + (size_t)s0 * C + 2 * l);
        float2 u1 = *(const float2*)(g_hh + (size_t)s1 * C + 2 * l);
        a0 += u0.x * eh0 + u1.x * eh1;
        a1 += u0.y * eh0 + u1.y * eh1;
        den += eh0 + eh1;
    }
    if (i < e_end) {
        int s0 = g_csrc[i];
        float t0 = 0.f;
        if (l == 0) t0 = __expf(lrelu(g_als_h[s0] + aldh));
        float eh0 = __shfl_sync(0xffffffffu, t0, 0);
        float2 u0 = *(const float2*)(g_hh + (size_t)s0 * C + 2 * l);
        a0 += u0.x * eh0; a1 += u0.y * eh0;
        den += eh0;
    }

    float inv = 1.f / (den + 1e-16f);
    float ht0 = tanhf(a0 * inv + __ldg(bh + 2 * l));
    float ht1 = tanhf(a1 * inv + __ldg(bh + 2 * l + 1));
    float2 Zv = *(const float2*)(g_Z + (size_t)d * C + 2 * l);
    float2 Hv = *(const float2*)(H + (size_t)d * C + 2 * l);
    float o0 = Zv.x * Hv.x + (1.f - Zv.x) * ht0;
    float o1 = Zv.y * Hv.y + (1.f - Zv.y) * ht1;
    *(float2*)(out + (size_t)d * C + 2 * l) = make_float2(o0, o1);
}

// ---------------- launch ----------------
extern "C" void kernel_launch(void* const* d_in, const int* in_sizes, int n_in,
                              void* d_out, int out_size)
{
    const float* X    = (const float*)d_in[0];
    const int*   ei   = (const int*)  d_in[1];
    const float* H    = (const float*)d_in[2];
    const float* Wz   = (const float*)d_in[3];
    const float* az_s = (const float*)d_in[4];
    const float* az_d = (const float*)d_in[5];
    const float* bz   = (const float*)d_in[6];
    const float* Wr   = (const float*)d_in[7];
    const float* ar_s = (const float*)d_in[8];
    const float* ar_d = (const float*)d_in[9];
    const float* br   = (const float*)d_in[10];
    const float* Wh   = (const float*)d_in[11];
    const float* ah_s = (const float*)d_in[12];
    const float* ah_d = (const float*)d_in[13];
    const float* bh   = (const float*)d_in[14];

    int n = in_sizes[0] / FIN;
    int E = in_sizes[1] / 2;
    const int* src = ei;
    const int* dst = ei + E;

    int nb = (n + SCAN_B - 1) / SCAN_B;
    int gemm_blocks = (n + 127) / 128;
    int warp_blocks = (n * 32 + 255) / 256;
    int eth = (E + 255) / 256;

    // gemm_zr stays at launch index 3 (the profiler's capture slot).
    k_zero_cnt<<<(n + 255) / 256, 256>>>(n);              // 0
    k_count<<<eth, 256>>>(dst, E);                        // 1
    k_scan1<<<nb, SCAN_B>>>(n);                           // 2
    gemm_zr<<<gemm_blocks, 256>>>(X, H, Wz, Wr, n);       // 3  <- profiled
    k_scan2<<<1, 512>>>(nb, n);                           // 4
    k_scan3<<<nb, SCAN_B>>>(n);                           // 5
    k_scatter<<<eth, 256>>>(src, dst, E);                 // 6

    node_attn_zr<<<warp_blocks, 256>>>(az_s, az_d, ar_s, ar_d, n);
    zr_node<<<warp_blocks, 256>>>(H, bz, br, n);

    gemm_h<<<gemm_blocks, 128>>>(X, Wh, n);
    node_attn_h<<<warp_blocks, 256>>>(ah_s, ah_d, n);
    h_node<<<warp_blocks, 256>>>(H, bh, (float*)d_out, n);
}

// round 10
// speedup vs baseline: 1.0785x; 1.0785x over previous
#include <cuda_runtime.h>
#include <cuda_fp16.h>
#include <cstdint>

#define N_MAX 50000
#define E_MAX 800000
#define C 64
#define FIN 128
#define D 192
#define NEG_SLOPE 0.2f
#define SCAN_B 512

// ---------------- scratch (static __device__; no allocations allowed) -------
// h matrices stored fp16 (gather traffic halved); all math in fp32.
__device__ __align__(16) __half g_hzr[N_MAX * 128];  // interleaved: [z2p,z2p+1,r2p,r2p+1]
__device__ __align__(16) __half g_hh[N_MAX * C];
__device__ __align__(16) float g_Z[N_MAX * C];
__device__ __align__(16) float g_HR[N_MAX * C];
__device__ float g_als_z[N_MAX], g_ald_z[N_MAX];
__device__ float g_als_r[N_MAX], g_ald_r[N_MAX];
__device__ float g_als_h[N_MAX], g_ald_h[N_MAX];
__device__ int g_cnt[N_MAX];
__device__ int g_rs[N_MAX + 1];     // CSR row starts (by dst)
__device__ int g_cur[N_MAX];        // scatter cursors
__device__ int g_bsum[512], g_boff[512];
__device__ int g_csrc[E_MAX];       // src node per CSR slot

// ---------------- helpers ----------------
__device__ __forceinline__ float lrelu(float x) { return x > 0.f ? x : NEG_SLOPE * x; }
__device__ __forceinline__ float sigmoidf_(float x) { return 1.f / (1.f + __expf(-x)); }

// ================= CSR build =================
__global__ void k_zero_cnt(int n) {
    int i = blockIdx.x * blockDim.x + threadIdx.x;
    if (i < n) g_cnt[i] = 0;
}
__global__ void k_count(const int* __restrict__ dst, int E) {
    int e = blockIdx.x * blockDim.x + threadIdx.x;
    if (e < E) atomicAdd(&g_cnt[dst[e]], 1);
}
__global__ void k_scan1(int n) {
    __shared__ int sm[SCAN_B];
    int i = blockIdx.x * SCAN_B + threadIdx.x;
    int c = (i < n) ? g_cnt[i] : 0;
    sm[threadIdx.x] = c;
    __syncthreads();
    for (int off = SCAN_B / 2; off; off >>= 1) {
        if (threadIdx.x < off) sm[threadIdx.x] += sm[threadIdx.x + off];
        __syncthreads();
    }
    if (threadIdx.x == 0) g_bsum[blockIdx.x] = sm[0];
}
__global__ void k_scan2(int nb, int n) {
    __shared__ int sm[512];
    int t = threadIdx.x;
    int v = (t < nb) ? g_bsum[t] : 0;
    sm[t] = v;
    __syncthreads();
    for (int off = 1; off < 512; off <<= 1) {
        int u = (t >= off) ? sm[t - off] : 0;
        __syncthreads();
        sm[t] += u;
        __syncthreads();
    }
    if (t < nb) g_boff[t] = sm[t] - v;
    if (t == 511) g_rs[n] = sm[511];
}
__global__ void k_scan3(int n) {
    __shared__ int sm[SCAN_B];
    int t = threadIdx.x;
    int i = blockIdx.x * SCAN_B + t;
    int c = (i < n) ? g_cnt[i] : 0;
    sm[t] = c;
    __syncthreads();
    for (int off = 1; off < SCAN_B; off <<= 1) {
        int v = (t >= off) ? sm[t - off] : 0;
        __syncthreads();
        sm[t] += v;
        __syncthreads();
    }
    if (i < n) {
        int excl = g_boff[blockIdx.x] + sm[t] - c;
        g_rs[i] = excl;
        g_cur[i] = excl;
    }
}
__global__ void k_scatter(const int* __restrict__ src, const int* __restrict__ dst, int E) {
    int e = blockIdx.x * blockDim.x + threadIdx.x;
    if (e < E) {
        int pos = atomicAdd(&g_cur[dst[e]], 1);
        g_csrc[pos] = src[e];
    }
}

// ================= GEMMs (R8-proven fp32 SIMT, fp16 epilogue) =================
// gemm_zr: BM=64, two gates fused, interleaved fp16 output.
__global__ void gemm_zr(const float* __restrict__ A1, const float* __restrict__ A2,
                        const float* __restrict__ B1, const float* __restrict__ B2, int n)
{
    __shared__ float As[16 * 64];
    __shared__ float Bs[16 * 128];

    int tid = threadIdx.x;
    int row0 = blockIdx.x * 64;
    int tr = tid >> 4;
    int tc = tid & 15;

    float acc[4][8];
#pragma unroll
    for (int i = 0; i < 4; i++)
#pragma unroll
        for (int j = 0; j < 8; j++) acc[i][j] = 0.f;

    int ar = tid >> 2;
    int akg = tid & 3;

    for (int k0 = 0; k0 < D; k0 += 16) {
        {
            int row = row0 + ar;
            int k = k0 + akg * 4;
            float4 v = make_float4(0.f, 0.f, 0.f, 0.f);
            if (row < n) {
                if (k < FIN) v = *(const float4*)(A1 + (size_t)row * FIN + k);
                else         v = *(const float4*)(A2 + (size_t)row * C + (k - FIN));
            }
            As[(akg * 4 + 0) * 64 + ar] = v.x;
            As[(akg * 4 + 1) * 64 + ar] = v.y;
            As[(akg * 4 + 2) * 64 + ar] = v.z;
            As[(akg * 4 + 3) * 64 + ar] = v.w;
        }
        {
            int i = tid * 8;
            int kk = i / 128;
            int col = i % 128;
            const float* B = (col < 64) ? B1 : B2;
            int bcol = col & 63;
            float4 v0 = *(const float4*)(B + (size_t)(k0 + kk) * 64 + bcol);
            *(float4*)(Bs + i) = v0;
            float4 v1 = *(const float4*)(B + (size_t)(k0 + kk) * 64 + bcol + 4);
            *(float4*)(Bs + i + 4) = v1;
        }
        __syncthreads();
#pragma unroll
        for (int kk = 0; kk < 16; kk++) {
            float4 a = *(const float4*)(As + kk * 64 + tr * 4);
            float av[4] = {a.x, a.y, a.z, a.w};
            float4 b0 = *(const float4*)(Bs + kk * 128 + tc * 4);
            float4 b1 = *(const float4*)(Bs + kk * 128 + 64 + tc * 4);
            float bv[8] = {b0.x, b0.y, b0.z, b0.w, b1.x, b1.y, b1.z, b1.w};
#pragma unroll
            for (int i = 0; i < 4; i++)
#pragma unroll
                for (int j = 0; j < 8; j++) acc[i][j] += av[i] * bv[j];
        }
        __syncthreads();
    }
    // fp16 interleaved store: halfs at tc*8.. = {z0,z1,r0,r1,z2,z3,r2,r3} of this thread
#pragma unroll
    for (int i = 0; i < 4; i++) {
        int row = row0 + tr * 4 + i;
        if (row >= n) continue;
        __half2 p0 = __floats2half2_rn(acc[i][0], acc[i][1]);
        __half2 p1 = __floats2half2_rn(acc[i][4], acc[i][5]);
        __half2 p2 = __floats2half2_rn(acc[i][2], acc[i][3]);
        __half2 p3 = __floats2half2_rn(acc[i][6], acc[i][7]);
        uint4 pk;
        pk.x = *(uint32_t*)&p0; pk.y = *(uint32_t*)&p1;
        pk.z = *(uint32_t*)&p2; pk.w = *(uint32_t*)&p3;
        *(uint4*)(g_hzr + (size_t)row * 128 + tc * 8) = pk;
    }
}

// gemm_h: BM=64, single gate, A2 = g_HR (fp32), fp16 output.
__global__ void gemm_h(const float* __restrict__ A1, const float* __restrict__ B1, int n)
{
    __shared__ float As[16 * 64];
    __shared__ float Bs[16 * 64];

    const float* A2 = g_HR;
    int tid = threadIdx.x;
    int row0 = blockIdx.x * 64;
    int tr = tid >> 4;
    int tc = tid & 15;

    float acc[4][4];
#pragma unroll
    for (int i = 0; i < 4; i++)
#pragma unroll
        for (int j = 0; j < 4; j++) acc[i][j] = 0.f;

    int ar = tid >> 2;
    int akg = tid & 3;

    for (int k0 = 0; k0 < D; k0 += 16) {
        {
            int row = row0 + ar;
            int k = k0 + akg * 4;
            float4 v = make_float4(0.f, 0.f, 0.f, 0.f);
            if (row < n) {
                if (k < FIN) v = *(const float4*)(A1 + (size_t)row * FIN + k);
                else         v = *(const float4*)(A2 + (size_t)row * C + (k - FIN));
            }
            As[(akg * 4 + 0) * 64 + ar] = v.x;
            As[(akg * 4 + 1) * 64 + ar] = v.y;
            As[(akg * 4 + 2) * 64 + ar] = v.z;
            As[(akg * 4 + 3) * 64 + ar] = v.w;
        }
        {
            int i = tid * 4;
            int kk = i / 64;
            int col = i % 64;
            float4 v0 = *(const float4*)(B1 + (size_t)(k0 + kk) * 64 + col);
            *(float4*)(Bs + i) = v0;
        }
        __syncthreads();
#pragma unroll
        for (int kk = 0; kk < 16; kk++) {
            float4 a = *(const float4*)(As + kk * 64 + tr * 4);
            float av[4] = {a.x, a.y, a.z, a.w};
            float4 b0 = *(const float4*)(Bs + kk * 64 + tc * 4);
            float bv[4] = {b0.x, b0.y, b0.z, b0.w};
#pragma unroll
            for (int i = 0; i < 4; i++)
#pragma unroll
                for (int j = 0; j < 4; j++) acc[i][j] += av[i] * bv[j];
        }
        __syncthreads();
    }
#pragma unroll
    for (int i = 0; i < 4; i++) {
        int row = row0 + tr * 4 + i;
        if (row >= n) continue;
        __half2 p0 = __floats2half2_rn(acc[i][0], acc[i][1]);
        __half2 p1 = __floats2half2_rn(acc[i][2], acc[i][3]);
        uint2 pk;
        pk.x = *(uint32_t*)&p0; pk.y = *(uint32_t*)&p1;
        *(uint2*)(g_hh + (size_t)row * C + tc * 4) = pk;
    }
}

// ================= attention scalars =================
__global__ void node_attn_zr(const float* __restrict__ az_s, const float* __restrict__ az_d,
                             const float* __restrict__ ar_s, const float* __restrict__ ar_d,
                             int n)
{
    int w = (blockIdx.x * blockDim.x + threadIdx.x) >> 5;
    if (w >= n) return;
    int l = threadIdx.x & 31;
    uint2 raw = *(const uint2*)(g_hzr + (size_t)w * 128 + 4 * l);
    float2 vz = __half22float2(*(__half2*)&raw.x);   // z2l, z2l+1
    float2 vr = __half22float2(*(__half2*)&raw.y);   // r2l, r2l+1
    float sz = vz.x * __ldg(az_s + 2 * l) + vz.y * __ldg(az_s + 2 * l + 1);
    float dz = vz.x * __ldg(az_d + 2 * l) + vz.y * __ldg(az_d + 2 * l + 1);
    float sr = vr.x * __ldg(ar_s + 2 * l) + vr.y * __ldg(ar_s + 2 * l + 1);
    float dr = vr.x * __ldg(ar_d + 2 * l) + vr.y * __ldg(ar_d + 2 * l + 1);
#pragma unroll
    for (int o = 16; o; o >>= 1) {
        sz += __shfl_xor_sync(0xffffffffu, sz, o);
        dz += __shfl_xor_sync(0xffffffffu, dz, o);
        sr += __shfl_xor_sync(0xffffffffu, sr, o);
        dr += __shfl_xor_sync(0xffffffffu, dr, o);
    }
    if (l == 0) { g_als_z[w] = sz; g_ald_z[w] = dz; g_als_r[w] = sr; g_ald_r[w] = dr; }
}

__global__ void node_attn_h(const float* __restrict__ a_src, const float* __restrict__ a_dst, int n)
{
    int w = (blockIdx.x * blockDim.x + threadIdx.x) >> 5;
    if (w >= n) return;
    int l = threadIdx.x & 31;
    float h0 = __half2float(g_hh[(size_t)w * C + l]);
    float h1 = __half2float(g_hh[(size_t)w * C + 32 + l]);
    float s = h0 * __ldg(a_src + l) + h1 * __ldg(a_src + 32 + l);
    float d = h0 * __ldg(a_dst + l) + h1 * __ldg(a_dst + 32 + l);
#pragma unroll
    for (int o = 16; o; o >>= 1) {
        s += __shfl_xor_sync(0xffffffffu, s, o);
        d += __shfl_xor_sync(0xffffffffu, d, o);
    }
    if (l == 0) { g_als_h[w] = s; g_ald_h[w] = d; }
}

// ================= fused per-dst accumulation =================
__global__ void zr_node(const float* __restrict__ H,
                        const float* __restrict__ bz, const float* __restrict__ br, int n)
{
    int d = (blockIdx.x * blockDim.x + threadIdx.x) >> 5;
    if (d >= n) return;
    int l = threadIdx.x & 31;

    float aldz = g_ald_z[d], aldr = g_ald_r[d];
    float alsz = g_als_z[d], alsr = g_als_r[d];

    float ez = 0.f, er = 0.f;
    if (l == 0)  ez = __expf(lrelu(alsz + aldz));
    if (l == 16) er = __expf(lrelu(alsr + aldr));
    ez = __shfl_sync(0xffffffffu, ez, 0);
    er = __shfl_sync(0xffffffffu, er, 16);

    uint2 raw = *(const uint2*)(g_hzr + (size_t)d * 128 + 4 * l);
    float2 vz = __half22float2(*(__half2*)&raw.x);
    float2 vr = __half22float2(*(__half2*)&raw.y);
    float az0 = vz.x * ez, az1 = vz.y * ez;
    float ar0 = vr.x * er, ar1 = vr.y * er;
    float denz = ez, denr = er;

    int b = g_rs[d], e_end = g_rs[d + 1];
    int i = b;
    for (; i + 1 < e_end; i += 2) {
        int s0 = g_csrc[i], s1 = g_csrc[i + 1];
        float t0 = 0.f, t1 = 0.f;
        if (l == 0)  t0 = __expf(lrelu(g_als_z[s0] + aldz));
        if (l == 1)  t1 = __expf(lrelu(g_als_z[s1] + aldz));
        if (l == 16) t0 = __expf(lrelu(g_als_r[s0] + aldr));
        if (l == 17) t1 = __expf(lrelu(g_als_r[s1] + aldr));
        float ez0 = __shfl_sync(0xffffffffu, t0, 0);
        float ez1 = __shfl_sync(0xffffffffu, t1, 1);
        float er0 = __shfl_sync(0xffffffffu, t0, 16);
        float er1 = __shfl_sync(0xffffffffu, t1, 17);
        uint2 r0 = *(const uint2*)(g_hzr + (size_t)s0 * 128 + 4 * l);
        uint2 r1 = *(const uint2*)(g_hzr + (size_t)s1 * 128 + 4 * l);
        float2 uz0 = __half22float2(*(__half2*)&r0.x);
        float2 ur0 = __half22float2(*(__half2*)&r0.y);
        float2 uz1 = __half22float2(*(__half2*)&r1.x);
        float2 ur1 = __half22float2(*(__half2*)&r1.y);
        az0 += uz0.x * ez0 + uz1.x * ez1;
        az1 += uz0.y * ez0 + uz1.y * ez1;
        ar0 += ur0.x * er0 + ur1.x * er1;
        ar1 += ur0.y * er0 + ur1.y * er1;
        denz += ez0 + ez1;
        denr += er0 + er1;
    }
    if (i < e_end) {
        int s0 = g_csrc[i];
        float t0 = 0.f;
        if (l == 0)  t0 = __expf(lrelu(g_als_z[s0] + aldz));
        if (l == 16) t0 = __expf(lrelu(g_als_r[s0] + aldr));
        float ez0 = __shfl_sync(0xffffffffu, t0, 0);
        float er0 = __shfl_sync(0xffffffffu, t0, 16);
        uint2 r0 = *(const uint2*)(g_hzr + (size_t)s0 * 128 + 4 * l);
        float2 uz0 = __half22float2(*(__half2*)&r0.x);
        float2 ur0 = __half22float2(*(__half2*)&r0.y);
        az0 += uz0.x * ez0; az1 += uz0.y * ez0;
        ar0 += ur0.x * er0; ar1 += ur0.y * er0;
        denz += ez0; denr += er0;
    }

    float iz = 1.f / (denz + 1e-16f), ir = 1.f / (denr + 1e-16f);
    float Z0 = sigmoidf_(az0 * iz + __ldg(bz + 2 * l));
    float Z1 = sigmoidf_(az1 * iz + __ldg(bz + 2 * l + 1));
    float R0 = sigmoidf_(ar0 * ir + __ldg(br + 2 * l));
    float R1 = sigmoidf_(ar1 * ir + __ldg(br + 2 * l + 1));
    float2 Hv = *(const float2*)(H + (size_t)d * C + 2 * l);
    *(float2*)(g_Z  + (size_t)d * C + 2 * l) = make_float2(Z0, Z1);
    *(float2*)(g_HR + (size_t)d * C + 2 * l) = make_float2(Hv.x * R0, Hv.y * R1);
}

__global__ void h_node(const float* __restrict__ H, const float* __restrict__ bh,
                       float* __restrict__ out, int n)
{
    int d = (blockIdx.x * blockDim.x + threadIdx.x) >> 5;
    if (d >= n) return;
    int l = threadIdx.x & 31;

    float aldh = g_ald_h[d];
    float alsh = g_als_h[d];

    float eh = 0.f;
    if (l == 0) eh = __expf(lrelu(alsh + aldh));
    eh = __shfl_sync(0xffffffffu, eh, 0);

    uint32_t raw = *(const uint32_t*)(g_hh + (size_t)d * C + 2 * l);
    float2 v = __half22float2(*(__half2*)&raw);
    float a0 = v.x * eh, a1 = v.y * eh;
    float den = eh;

    int b = g_rs[d], e_end = g_rs[d + 1];
    int i = b;
    for (; i + 1 < e_end; i += 2) {
        int s0 = g_csrc[i], s1 = g_csrc[i + 1];
        float t0 = 0.f, t1 = 0.f;
        if (l == 0) t0 = __expf(lrelu(g_als_h[s0] + aldh));
        if (l == 1) t1 = __expf(lrelu(g_als_h[s1] + aldh));
        float eh0 = __shfl_sync(0xffffffffu, t0, 0);
        float eh1 = __shfl_sync(0xffffffffu, t1, 1);
        uint32_t w0 = *(const uint32_t*)(g_hh + (size_t)s0 * C + 2 * l);
        uint32_t w1 = *(const uint32_t*)(g_hh + (size_t)s1 * C + 2 * l);
        float2 u0 = __half22float2(*(__half2*)&w0);
        float2 u1 = __half22float2(*(__half2*)&w1);
        a0 += u0.x * eh0 + u1.x * eh1;
        a1 += u0.y * eh0 + u1.y * eh1;
        den += eh0 + eh1;
    }
    if (i < e_end) {
        int s0 = g_csrc[i];
        float t0 = 0.f;
        if (l == 0) t0 = __expf(lrelu(g_als_h[s0] + aldh));
        float eh0 = __shfl_sync(0xffffffffu, t0, 0);
        uint32_t w0 = *(const uint32_t*)(g_hh + (size_t)s0 * C + 2 * l);
        float2 u0 = __half22float2(*(__half2*)&w0);
        a0 += u0.x * eh0; a1 += u0.y * eh0;
        den += eh0;
    }

    float inv = 1.f / (den + 1e-16f);
    float ht0 = tanhf(a0 * inv + __ldg(bh + 2 * l));
    float ht1 = tanhf(a1 * inv + __ldg(bh + 2 * l + 1));
    float2 Zv = *(const float2*)(g_Z + (size_t)d * C + 2 * l);
    float2 Hv = *(const float2*)(H + (size_t)d * C + 2 * l);
    float o0 = Zv.x * Hv.x + (1.f - Zv.x) * ht0;
    float o1 = Zv.y * Hv.y + (1.f - Zv.y) * ht1;
    *(float2*)(out + (size_t)d * C + 2 * l) = make_float2(o0, o1);
}

// ---------------- launch ----------------
extern "C" void kernel_launch(void* const* d_in, const int* in_sizes, int n_in,
                              void* d_out, int out_size)
{
    const float* X    = (const float*)d_in[0];
    const int*   ei   = (const int*)  d_in[1];
    const float* H    = (const float*)d_in[2];
    const float* Wz   = (const float*)d_in[3];
    const float* az_s = (const float*)d_in[4];
    const float* az_d = (const float*)d_in[5];
    const float* bz   = (const float*)d_in[6];
    const float* Wr   = (const float*)d_in[7];
    const float* ar_s = (const float*)d_in[8];
    const float* ar_d = (const float*)d_in[9];
    const float* br   = (const float*)d_in[10];
    const float* Wh   = (const float*)d_in[11];
    const float* ah_s = (const float*)d_in[12];
    const float* ah_d = (const float*)d_in[13];
    const float* bh   = (const float*)d_in[14];

    int n = in_sizes[0] / FIN;
    int E = in_sizes[1] / 2;
    const int* src = ei;
    const int* dst = ei + E;

    int nb = (n + SCAN_B - 1) / SCAN_B;
    int gemm_blocks = (n + 63) / 64;
    int warp_blocks = (n * 32 + 255) / 256;
    int eth = (E + 255) / 256;

    // gemm_zr stays at launch index 3 (the profiler's capture slot).
    k_zero_cnt<<<(n + 255) / 256, 256>>>(n);              // 0
    k_count<<<eth, 256>>>(dst, E);                        // 1
    k_scan1<<<nb, SCAN_B>>>(n);                           // 2
    gemm_zr<<<gemm_blocks, 256>>>(X, H, Wz, Wr, n);       // 3  <- profiled
    k_scan2<<<1, 512>>>(nb, n);                           // 4
    k_scan3<<<nb, SCAN_B>>>(n);                           // 5
    k_scatter<<<eth, 256>>>(src, dst, E);                 // 6

    node_attn_zr<<<warp_blocks, 256>>>(az_s, az_d, ar_s, ar_d, n);
    zr_node<<<warp_blocks, 256>>>(H, bz, br, n);

    gemm_h<<<gemm_blocks, 256>>>(X, Wh, n);
    node_attn_h<<<warp_blocks, 256>>>(ah_s, ah_d, n);
    h_node<<<warp_blocks, 256>>>(H, bh, (float*)d_out, n);
}

// round 11
// speedup vs baseline: 1.3792x; 1.2789x over previous
#include <cuda_runtime.h>
#include <cuda_fp16.h>
#include <mma.h>
#include <cstdint>

using namespace nvcuda;

#define N_MAX 50000
#define E_MAX 800000
#define C 64
#define FIN 128
#define D 192
#define NEG_SLOPE 0.2f
#define SCAN_B 512

// ---------------- scratch (static __device__; no allocations allowed) -------
// h matrices stored fp16 (gather traffic halved); accumulation math in fp32.
__device__ __align__(16) __half g_hzr[N_MAX * 128];  // interleaved: [z2p,z2p+1,r2p,r2p+1]
__device__ __align__(16) __half g_hh[N_MAX * C];
__device__ __align__(16) __half g_HR[N_MAX * C];     // H*R, feeds gemm_h only
__device__ __align__(16) float g_Z[N_MAX * C];
__device__ float g_als_z[N_MAX], g_ald_z[N_MAX];
__device__ float g_als_r[N_MAX], g_ald_r[N_MAX];
__device__ float g_als_h[N_MAX], g_ald_h[N_MAX];
__device__ int g_cnt[N_MAX];
__device__ int g_rs[N_MAX + 1];
__device__ int g_cur[N_MAX];
__device__ int g_bsum[512], g_boff[512];
__device__ int g_csrc[E_MAX];

// ---------------- helpers ----------------
__device__ __forceinline__ float lrelu(float x) { return x > 0.f ? x : NEG_SLOPE * x; }
__device__ __forceinline__ float sigmoidf_(float x) { return 1.f / (1.f + __expf(-x)); }

// ================= CSR build =================
__global__ void k_zero_cnt(int n) {
    int i = blockIdx.x * blockDim.x + threadIdx.x;
    if (i < n) g_cnt[i] = 0;
}
__global__ void k_count(const int* __restrict__ dst, int E) {
    int e = blockIdx.x * blockDim.x + threadIdx.x;
    if (e < E) atomicAdd(&g_cnt[dst[e]], 1);
}
__global__ void k_scan1(int n) {
    __shared__ int sm[SCAN_B];
    int i = blockIdx.x * SCAN_B + threadIdx.x;
    int c = (i < n) ? g_cnt[i] : 0;
    sm[threadIdx.x] = c;
    __syncthreads();
    for (int off = SCAN_B / 2; off; off >>= 1) {
        if (threadIdx.x < off) sm[threadIdx.x] += sm[threadIdx.x + off];
        __syncthreads();
    }
    if (threadIdx.x == 0) g_bsum[blockIdx.x] = sm[0];
}
__global__ void k_scan2(int nb, int n) {
    __shared__ int sm[512];
    int t = threadIdx.x;
    int v = (t < nb) ? g_bsum[t] : 0;
    sm[t] = v;
    __syncthreads();
    for (int off = 1; off < 512; off <<= 1) {
        int u = (t >= off) ? sm[t - off] : 0;
        __syncthreads();
        sm[t] += u;
        __syncthreads();
    }
    if (t < nb) g_boff[t] = sm[t] - v;
    if (t == 511) g_rs[n] = sm[511];
}
__global__ void k_scan3(int n) {
    __shared__ int sm[SCAN_B];
    int t = threadIdx.x;
    int i = blockIdx.x * SCAN_B + t;
    int c = (i < n) ? g_cnt[i] : 0;
    sm[t] = c;
    __syncthreads();
    for (int off = 1; off < SCAN_B; off <<= 1) {
        int v = (t >= off) ? sm[t - off] : 0;
        __syncthreads();
        sm[t] += v;
        __syncthreads();
    }
    if (i < n) {
        int excl = g_boff[blockIdx.x] + sm[t] - c;
        g_rs[i] = excl;
        g_cur[i] = excl;
    }
}
__global__ void k_scatter(const int* __restrict__ src, const int* __restrict__ dst, int E) {
    int e = blockIdx.x * blockDim.x + threadIdx.x;
    if (e < E) {
        int pos = atomicAdd(&g_cur[dst[e]], 1);
        g_csrc[pos] = src[e];
    }
}

// ================= fp16 wmma GEMMs (fp32 accumulate, single pass) =============
// O = [A1 | A2] (n x 192) @ B (192 x 64) per gate.
#define AH_LD 24     // 16 + 8 pad (halves)
#define BH_LD_ZR 136 // 128 + 8 pad
#define BH_LD_H 72   // 64 + 8
#define CS_LD_ZR 132 // floats, mult of 4
#define CS_LD_H 68

// gemm_zr: BM=64, BN=128 (z|r interleaved pairs), 8 warps as 4x2 (warp tile 16x64).
__global__ void __launch_bounds__(256)
gemm_zr(const float* __restrict__ A1, const float* __restrict__ A2,
        const float* __restrict__ B1, const float* __restrict__ B2, int n)
{
    __shared__ __half Ah[64 * AH_LD];
    __shared__ __half Bh[16 * BH_LD_ZR];
    __shared__ float Cs[64 * CS_LD_ZR];

    int tid = threadIdx.x, warp = tid >> 5;
    int warp_m = warp >> 1, warp_n = warp & 1;
    int row0 = blockIdx.x * 64;

    wmma::fragment<wmma::accumulator, 16, 16, 16, float> acc[4];
#pragma unroll
    for (int j = 0; j < 4; j++) wmma::fill_fragment(acc[j], 0.f);

    int a_row = tid >> 2;            // 0..63
    int a_kg = (tid & 3) * 4;        // 0,4,8,12
    int b_kk = tid >> 4;             // 0..15
    int b_q = tid & 15;              // pair-group

    for (int k0 = 0; k0 < D; k0 += 16) {
        // --- A tile (64 x 16) -> half ---
        {
            int grow = row0 + a_row;
            int k = k0 + a_kg;
            float4 v = make_float4(0.f, 0.f, 0.f, 0.f);
            if (grow < n) {
                if (k < FIN) v = *(const float4*)(A1 + (size_t)grow * FIN + k);
                else         v = *(const float4*)(A2 + (size_t)grow * C + (k - FIN));
            }
            __half2* pa = (__half2*)(Ah + a_row * AH_LD + a_kg);
            pa[0] = __floats2half2_rn(v.x, v.y);
            pa[1] = __floats2half2_rn(v.z, v.w);
        }
        // --- B tile (16 x 128 physical, z/r interleaved pairs) -> half ---
        {
            float4 vz = *(const float4*)(B1 + (size_t)(k0 + b_kk) * C + b_q * 4);
            float4 vr = *(const float4*)(B2 + (size_t)(k0 + b_kk) * C + b_q * 4);
            __half2* pb = (__half2*)(Bh + b_kk * BH_LD_ZR + b_q * 8);
            pb[0] = __floats2half2_rn(vz.x, vz.y);
            pb[1] = __floats2half2_rn(vr.x, vr.y);
            pb[2] = __floats2half2_rn(vz.z, vz.w);
            pb[3] = __floats2half2_rn(vr.z, vr.w);
        }
        __syncthreads();

        wmma::fragment<wmma::matrix_a, 16, 16, 16, __half, wmma::row_major> fa;
        wmma::load_matrix_sync(fa, Ah + warp_m * 16 * AH_LD, AH_LD);
#pragma unroll
        for (int j = 0; j < 4; j++) {
            wmma::fragment<wmma::matrix_b, 16, 16, 16, __half, wmma::row_major> fb;
            wmma::load_matrix_sync(fb, Bh + warp_n * 64 + j * 16, BH_LD_ZR);
            wmma::mma_sync(acc[j], fa, fb, acc[j]);
        }
        __syncthreads();
    }

    // epilogue: stage fp32 in smem, convert to packed half
#pragma unroll
    for (int j = 0; j < 4; j++)
        wmma::store_matrix_sync(Cs + warp_m * 16 * CS_LD_ZR + warp_n * 64 + j * 16,
                                acc[j], CS_LD_ZR, wmma::mem_row_major);
    __syncthreads();
    {
        int r = tid >> 2, c0 = (tid & 3) * 32;
        int grow = row0 + r;
        if (grow < n) {
#pragma unroll
            for (int c = 0; c < 32; c += 8) {
                float4 f0 = *(const float4*)(Cs + r * CS_LD_ZR + c0 + c);
                float4 f1 = *(const float4*)(Cs + r * CS_LD_ZR + c0 + c + 4);
                __half2 h0 = __floats2half2_rn(f0.x, f0.y);
                __half2 h1 = __floats2half2_rn(f0.z, f0.w);
                __half2 h2 = __floats2half2_rn(f1.x, f1.y);
                __half2 h3 = __floats2half2_rn(f1.z, f1.w);
                uint4 pk;
                pk.x = *(uint32_t*)&h0; pk.y = *(uint32_t*)&h1;
                pk.z = *(uint32_t*)&h2; pk.w = *(uint32_t*)&h3;
                *(uint4*)(g_hzr + (size_t)grow * 128 + c0 + c) = pk;
            }
        }
    }
}

// gemm_h: BM=64, BN=64, 8 warps as 4x2 (warp tile 16x32), A2 = g_HR (half).
__global__ void __launch_bounds__(256)
gemm_h(const float* __restrict__ A1, const float* __restrict__ B1, int n)
{
    __shared__ __half Ah[64 * AH_LD];
    __shared__ __half Bh[16 * BH_LD_H];
    __shared__ float Cs[64 * CS_LD_H];

    int tid = threadIdx.x, warp = tid >> 5;
    int warp_m = warp >> 1, warp_n = warp & 1;
    int row0 = blockIdx.x * 64;

    wmma::fragment<wmma::accumulator, 16, 16, 16, float> acc[2];
#pragma unroll
    for (int j = 0; j < 2; j++) wmma::fill_fragment(acc[j], 0.f);

    int a_row = tid >> 2;
    int a_kg = (tid & 3) * 4;
    int b_kk = tid >> 4;
    int b_col = (tid & 15) * 4;

    for (int k0 = 0; k0 < D; k0 += 16) {
        // --- A tile: X (float) or g_HR (half) ---
        {
            int grow = row0 + a_row;
            int k = k0 + a_kg;
            __half2 p0, p1;
            if (grow < n && k < FIN) {
                float4 v = *(const float4*)(A1 + (size_t)grow * FIN + k);
                p0 = __floats2half2_rn(v.x, v.y);
                p1 = __floats2half2_rn(v.z, v.w);
            } else if (grow < n) {
                uint2 raw = *(const uint2*)(g_HR + (size_t)grow * C + (k - FIN));
                p0 = *(__half2*)&raw.x;
                p1 = *(__half2*)&raw.y;
            } else {
                p0 = __floats2half2_rn(0.f, 0.f);
                p1 = p0;
            }
            __half2* pa = (__half2*)(Ah + a_row * AH_LD + a_kg);
            pa[0] = p0; pa[1] = p1;
        }
        // --- B tile (16 x 64) ---
        {
            float4 v = *(const float4*)(B1 + (size_t)(k0 + b_kk) * C + b_col);
            __half2* pb = (__half2*)(Bh + b_kk * BH_LD_H + b_col);
            pb[0] = __floats2half2_rn(v.x, v.y);
            pb[1] = __floats2half2_rn(v.z, v.w);
        }
        __syncthreads();

        wmma::fragment<wmma::matrix_a, 16, 16, 16, __half, wmma::row_major> fa;
        wmma::load_matrix_sync(fa, Ah + warp_m * 16 * AH_LD, AH_LD);
#pragma unroll
        for (int j = 0; j < 2; j++) {
            wmma::fragment<wmma::matrix_b, 16, 16, 16, __half, wmma::row_major> fb;
            wmma::load_matrix_sync(fb, Bh + warp_n * 32 + j * 16, BH_LD_H);
            wmma::mma_sync(acc[j], fa, fb, acc[j]);
        }
        __syncthreads();
    }

#pragma unroll
    for (int j = 0; j < 2; j++)
        wmma::store_matrix_sync(Cs + warp_m * 16 * CS_LD_H + warp_n * 32 + j * 16,
                                acc[j], CS_LD_H, wmma::mem_row_major);
    __syncthreads();
    {
        int r = tid >> 2, c0 = (tid & 3) * 16;
        int grow = row0 + r;
        if (grow < n) {
#pragma unroll
            for (int c = 0; c < 16; c += 8) {
                float4 f0 = *(const float4*)(Cs + r * CS_LD_H + c0 + c);
                float4 f1 = *(const float4*)(Cs + r * CS_LD_H + c0 + c + 4);
                __half2 h0 = __floats2half2_rn(f0.x, f0.y);
                __half2 h1 = __floats2half2_rn(f0.z, f0.w);
                __half2 h2 = __floats2half2_rn(f1.x, f1.y);
                __half2 h3 = __floats2half2_rn(f1.z, f1.w);
                uint4 pk;
                pk.x = *(uint32_t*)&h0; pk.y = *(uint32_t*)&h1;
                pk.z = *(uint32_t*)&h2; pk.w = *(uint32_t*)&h3;
                *(uint4*)(g_hh + (size_t)grow * C + c0 + c) = pk;
            }
        }
    }
}

// ================= attention scalars =================
__global__ void node_attn_zr(const float* __restrict__ az_s, const float* __restrict__ az_d,
                             const float* __restrict__ ar_s, const float* __restrict__ ar_d,
                             int n)
{
    int w = (blockIdx.x * blockDim.x + threadIdx.x) >> 5;
    if (w >= n) return;
    int l = threadIdx.x & 31;
    uint2 raw = *(const uint2*)(g_hzr + (size_t)w * 128 + 4 * l);
    float2 vz = __half22float2(*(__half2*)&raw.x);
    float2 vr = __half22float2(*(__half2*)&raw.y);
    float sz = vz.x * __ldg(az_s + 2 * l) + vz.y * __ldg(az_s + 2 * l + 1);
    float dz = vz.x * __ldg(az_d + 2 * l) + vz.y * __ldg(az_d + 2 * l + 1);
    float sr = vr.x * __ldg(ar_s + 2 * l) + vr.y * __ldg(ar_s + 2 * l + 1);
    float dr = vr.x * __ldg(ar_d + 2 * l) + vr.y * __ldg(ar_d + 2 * l + 1);
#pragma unroll
    for (int o = 16; o; o >>= 1) {
        sz += __shfl_xor_sync(0xffffffffu, sz, o);
        dz += __shfl_xor_sync(0xffffffffu, dz, o);
        sr += __shfl_xor_sync(0xffffffffu, sr, o);
        dr += __shfl_xor_sync(0xffffffffu, dr, o);
    }
    if (l == 0) { g_als_z[w] = sz; g_ald_z[w] = dz; g_als_r[w] = sr; g_ald_r[w] = dr; }
}

__global__ void node_attn_h(const float* __restrict__ a_src, const float* __restrict__ a_dst, int n)
{
    int w = (blockIdx.x * blockDim.x + threadIdx.x) >> 5;
    if (w >= n) return;
    int l = threadIdx.x & 31;
    float h0 = __half2float(g_hh[(size_t)w * C + l]);
    float h1 = __half2float(g_hh[(size_t)w * C + 32 + l]);
    float s = h0 * __ldg(a_src + l) + h1 * __ldg(a_src + 32 + l);
    float d = h0 * __ldg(a_dst + l) + h1 * __ldg(a_dst + 32 + l);
#pragma unroll
    for (int o = 16; o; o >>= 1) {
        s += __shfl_xor_sync(0xffffffffu, s, o);
        d += __shfl_xor_sync(0xffffffffu, d, o);
    }
    if (l == 0) { g_als_h[w] = s; g_ald_h[w] = d; }
}

// ================= fused per-dst accumulation =================
__global__ void zr_node(const float* __restrict__ H,
                        const float* __restrict__ bz, const float* __restrict__ br, int n)
{
    int d = (blockIdx.x * blockDim.x + threadIdx.x) >> 5;
    if (d >= n) return;
    int l = threadIdx.x & 31;

    float aldz = g_ald_z[d], aldr = g_ald_r[d];
    float alsz = g_als_z[d], alsr = g_als_r[d];

    float ez = 0.f, er = 0.f;
    if (l == 0)  ez = __expf(lrelu(alsz + aldz));
    if (l == 16) er = __expf(lrelu(alsr + aldr));
    ez = __shfl_sync(0xffffffffu, ez, 0);
    er = __shfl_sync(0xffffffffu, er, 16);

    uint2 raw = *(const uint2*)(g_hzr + (size_t)d * 128 + 4 * l);
    float2 vz = __half22float2(*(__half2*)&raw.x);
    float2 vr = __half22float2(*(__half2*)&raw.y);
    float az0 = vz.x * ez, az1 = vz.y * ez;
    float ar0 = vr.x * er, ar1 = vr.y * er;
    float denz = ez, denr = er;

    int b = g_rs[d], e_end = g_rs[d + 1];
    int i = b;
    for (; i + 1 < e_end; i += 2) {
        int s0 = g_csrc[i], s1 = g_csrc[i + 1];
        float t0 = 0.f, t1 = 0.f;
        if (l == 0)  t0 = __expf(lrelu(g_als_z[s0] + aldz));
        if (l == 1)  t1 = __expf(lrelu(g_als_z[s1] + aldz));
        if (l == 16) t0 = __expf(lrelu(g_als_r[s0] + aldr));
        if (l == 17) t1 = __expf(lrelu(g_als_r[s1] + aldr));
        float ez0 = __shfl_sync(0xffffffffu, t0, 0);
        float ez1 = __shfl_sync(0xffffffffu, t1, 1);
        float er0 = __shfl_sync(0xffffffffu, t0, 16);
        float er1 = __shfl_sync(0xffffffffu, t1, 17);
        uint2 r0 = *(const uint2*)(g_hzr + (size_t)s0 * 128 + 4 * l);
        uint2 r1 = *(const uint2*)(g_hzr + (size_t)s1 * 128 + 4 * l);
        float2 uz0 = __half22float2(*(__half2*)&r0.x);
        float2 ur0 = __half22float2(*(__half2*)&r0.y);
        float2 uz1 = __half22float2(*(__half2*)&r1.x);
        float2 ur1 = __half22float2(*(__half2*)&r1.y);
        az0 += uz0.x * ez0 + uz1.x * ez1;
        az1 += uz0.y * ez0 + uz1.y * ez1;
        ar0 += ur0.x * er0 + ur1.x * er1;
        ar1 += ur0.y * er0 + ur1.y * er1;
        denz += ez0 + ez1;
        denr += er0 + er1;
    }
    if (i < e_end) {
        int s0 = g_csrc[i];
        float t0 = 0.f;
        if (l == 0)  t0 = __expf(lrelu(g_als_z[s0] + aldz));
        if (l == 16) t0 = __expf(lrelu(g_als_r[s0] + aldr));
        float ez0 = __shfl_sync(0xffffffffu, t0, 0);
        float er0 = __shfl_sync(0xffffffffu, t0, 16);
        uint2 r0 = *(const uint2*)(g_hzr + (size_t)s0 * 128 + 4 * l);
        float2 uz0 = __half22float2(*(__half2*)&r0.x);
        float2 ur0 = __half22float2(*(__half2*)&r0.y);
        az0 += uz0.x * ez0; az1 += uz0.y * ez0;
        ar0 += ur0.x * er0; ar1 += ur0.y * er0;
        denz += ez0; denr += er0;
    }

    float iz = 1.f / (denz + 1e-16f), ir = 1.f / (denr + 1e-16f);
    float Z0 = sigmoidf_(az0 * iz + __ldg(bz + 2 * l));
    float Z1 = sigmoidf_(az1 * iz + __ldg(bz + 2 * l + 1));
    float R0 = sigmoidf_(ar0 * ir + __ldg(br + 2 * l));
    float R1 = sigmoidf_(ar1 * ir + __ldg(br + 2 * l + 1));
    float2 Hv = *(const float2*)(H + (size_t)d * C + 2 * l);
    *(float2*)(g_Z + (size_t)d * C + 2 * l) = make_float2(Z0, Z1);
    __half2 hr = __floats2half2_rn(Hv.x * R0, Hv.y * R1);
    *(uint32_t*)(g_HR + (size_t)d * C + 2 * l) = *(uint32_t*)&hr;
}

__global__ void h_node(const float* __restrict__ H, const float* __restrict__ bh,
                       float* __restrict__ out, int n)
{
    int d = (blockIdx.x * blockDim.x + threadIdx.x) >> 5;
    if (d >= n) return;
    int l = threadIdx.x & 31;

    float aldh = g_ald_h[d];
    float alsh = g_als_h[d];

    float eh = 0.f;
    if (l == 0) eh = __expf(lrelu(alsh + aldh));
    eh = __shfl_sync(0xffffffffu, eh, 0);

    uint32_t raw = *(const uint32_t*)(g_hh + (size_t)d * C + 2 * l);
    float2 v = __half22float2(*(__half2*)&raw);
    float a0 = v.x * eh, a1 = v.y * eh;
    float den = eh;

    int b = g_rs[d], e_end = g_rs[d + 1];
    int i = b;
    for (; i + 1 < e_end; i += 2) {
        int s0 = g_csrc[i], s1 = g_csrc[i + 1];
        float t0 = 0.f, t1 = 0.f;
        if (l == 0) t0 = __expf(lrelu(g_als_h[s0] + aldh));
        if (l == 1) t1 = __expf(lrelu(g_als_h[s1] + aldh));
        float eh0 = __shfl_sync(0xffffffffu, t0, 0);
        float eh1 = __shfl_sync(0xffffffffu, t1, 1);
        uint32_t w0 = *(const uint32_t*)(g_hh + (size_t)s0 * C + 2 * l);
        uint32_t w1 = *(const uint32_t*)(g_hh + (size_t)s1 * C + 2 * l);
        float2 u0 = __half22float2(*(__half2*)&w0);
        float2 u1 = __half22float2(*(__half2*)&w1);
        a0 += u0.x * eh0 + u1.x * eh1;
        a1 += u0.y * eh0 + u1.y * eh1;
        den += eh0 + eh1;
    }
    if (i < e_end) {
        int s0 = g_csrc[i];
        float t0 = 0.f;
        if (l == 0) t0 = __expf(lrelu(g_als_h[s0] + aldh));
        float eh0 = __shfl_sync(0xffffffffu, t0, 0);
        uint32_t w0 = *(const uint32_t*)(g_hh + (size_t)s0 * C + 2 * l);
        float2 u0 = __half22float2(*(__half2*)&w0);
        a0 += u0.x * eh0; a1 += u0.y * eh0;
        den += eh0;
    }

    float inv = 1.f / (den + 1e-16f);
    float ht0 = tanhf(a0 * inv + __ldg(bh + 2 * l));
    float ht1 = tanhf(a1 * inv + __ldg(bh + 2 * l + 1));
    float2 Zv = *(const float2*)(g_Z + (size_t)d * C + 2 * l);
    float2 Hv = *(const float2*)(H + (size_t)d * C + 2 * l);
    float o0 = Zv.x * Hv.x + (1.f - Zv.x) * ht0;
    float o1 = Zv.y * Hv.y + (1.f - Zv.y) * ht1;
    *(float2*)(out + (size_t)d * C + 2 * l) = make_float2(o0, o1);
}

// ---------------- launch ----------------
extern "C" void kernel_launch(void* const* d_in, const int* in_sizes, int n_in,
                              void* d_out, int out_size)
{
    const float* X    = (const float*)d_in[0];
    const int*   ei   = (const int*)  d_in[1];
    const float* H    = (const float*)d_in[2];
    const float* Wz   = (const float*)d_in[3];
    const float* az_s = (const float*)d_in[4];
    const float* az_d = (const float*)d_in[5];
    const float* bz   = (const float*)d_in[6];
    const float* Wr   = (const float*)d_in[7];
    const float* ar_s = (const float*)d_in[8];
    const float* ar_d = (const float*)d_in[9];
    const float* br   = (const float*)d_in[10];
    const float* Wh   = (const float*)d_in[11];
    const float* ah_s = (const float*)d_in[12];
    const float* ah_d = (const float*)d_in[13];
    const float* bh   = (const float*)d_in[14];

    int n = in_sizes[0] / FIN;
    int E = in_sizes[1] / 2;
    const int* src = ei;
    const int* dst = ei + E;

    int nb = (n + SCAN_B - 1) / SCAN_B;
    int gemm_blocks = (n + 63) / 64;
    int warp_blocks = (n * 32 + 255) / 256;
    int eth = (E + 255) / 256;

    // gemm_zr stays at launch index 3 (the profiler's capture slot).
    k_zero_cnt<<<(n + 255) / 256, 256>>>(n);              // 0
    k_count<<<eth, 256>>>(dst, E);                        // 1
    k_scan1<<<nb, SCAN_B>>>(n);                           // 2
    gemm_zr<<<gemm_blocks, 256>>>(X, H, Wz, Wr, n);       // 3  <- profiled
    k_scan2<<<1, 512>>>(nb, n);                           // 4
    k_scan3<<<nb, SCAN_B>>>(n);                           // 5
    k_scatter<<<eth, 256>>>(src, dst, E);                 // 6

    node_attn_zr<<<warp_blocks, 256>>>(az_s, az_d, ar_s, ar_d, n);
    zr_node<<<warp_blocks, 256>>>(H, bz, br, n);

    gemm_h<<<gemm_blocks, 256>>>(X, Wh, n);
    node_attn_h<<<warp_blocks, 256>>>(ah_s, ah_d, n);
    h_node<<<warp_blocks, 256>>>(H, bh, (float*)d_out, n);
}

// round 12
// speedup vs baseline: 1.4475x; 1.0495x over previous
#include <cuda_runtime.h>
#include <cuda_fp16.h>
#include <mma.h>
#include <cstdint>

using namespace nvcuda;

#define N_MAX 50000
#define E_MAX 800000
#define C 64
#define FIN 128
#define D 192
#define NEG_SLOPE 0.2f
#define SCAN_B 512

// ---------------- scratch (static __device__; no allocations allowed) -------
__device__ __align__(16) __half g_hzr[N_MAX * 128];  // interleaved: [z2p,z2p+1,r2p,r2p+1]
__device__ __align__(16) __half g_hh[N_MAX * C];
__device__ __align__(16) __half g_HR[N_MAX * C];     // H*R, feeds gemm_h only
__device__ __align__(16) float g_Z[N_MAX * C];
__device__ float g_als_z[N_MAX], g_ald_z[N_MAX];
__device__ float g_als_r[N_MAX], g_ald_r[N_MAX];
__device__ float g_als_h[N_MAX], g_ald_h[N_MAX];
__device__ int g_cnt[N_MAX];
__device__ int g_rs[N_MAX + 1];
__device__ int g_cur[N_MAX];
__device__ int g_bsum[512], g_boff[512];
__device__ int g_csrc[E_MAX];

// ---------------- helpers ----------------
__device__ __forceinline__ float lrelu(float x) { return x > 0.f ? x : NEG_SLOPE * x; }
__device__ __forceinline__ float sigmoidf_(float x) { return 1.f / (1.f + __expf(-x)); }

// ================= CSR build =================
__global__ void k_zero_cnt(int n) {
    int i = blockIdx.x * blockDim.x + threadIdx.x;
    if (i < n) g_cnt[i] = 0;
}
__global__ void k_count(const int* __restrict__ dst, int E) {
    int e = blockIdx.x * blockDim.x + threadIdx.x;
    if (e < E) atomicAdd(&g_cnt[dst[e]], 1);
}
__global__ void k_scan1(int n) {
    __shared__ int sm[SCAN_B];
    int i = blockIdx.x * SCAN_B + threadIdx.x;
    int c = (i < n) ? g_cnt[i] : 0;
    sm[threadIdx.x] = c;
    __syncthreads();
    for (int off = SCAN_B / 2; off; off >>= 1) {
        if (threadIdx.x < off) sm[threadIdx.x] += sm[threadIdx.x + off];
        __syncthreads();
    }
    if (threadIdx.x == 0) g_bsum[blockIdx.x] = sm[0];
}
__global__ void k_scan2(int nb, int n) {
    __shared__ int sm[512];
    int t = threadIdx.x;
    int v = (t < nb) ? g_bsum[t] : 0;
    sm[t] = v;
    __syncthreads();
    for (int off = 1; off < 512; off <<= 1) {
        int u = (t >= off) ? sm[t - off] : 0;
        __syncthreads();
        sm[t] += u;
        __syncthreads();
    }
    if (t < nb) g_boff[t] = sm[t] - v;
    if (t == 511) g_rs[n] = sm[511];
}
__global__ void k_scan3(int n) {
    __shared__ int sm[SCAN_B];
    int t = threadIdx.x;
    int i = blockIdx.x * SCAN_B + t;
    int c = (i < n) ? g_cnt[i] : 0;
    sm[t] = c;
    __syncthreads();
    for (int off = 1; off < SCAN_B; off <<= 1) {
        int v = (t >= off) ? sm[t - off] : 0;
        __syncthreads();
        sm[t] += v;
        __syncthreads();
    }
    if (i < n) {
        int excl = g_boff[blockIdx.x] + sm[t] - c;
        g_rs[i] = excl;
        g_cur[i] = excl;
    }
}
__global__ void k_scatter(const int* __restrict__ src, const int* __restrict__ dst, int E) {
    int e = blockIdx.x * blockDim.x + threadIdx.x;
    if (e < E) {
        int pos = atomicAdd(&g_cur[dst[e]], 1);
        g_csrc[pos] = src[e];
    }
}

// ================= fp16 wmma GEMMs (fp32 accumulate, single pass) =============
#define AH_LD 24
#define BH_LD_ZR 136
#define BH_LD_H 72
#define CS_LD_ZR 132
#define CS_LD_H 68

// gemm_zr: BM=64, BN=128 (z|r interleaved pairs), 8 warps as 4x2 (warp tile 16x64).
__global__ void __launch_bounds__(256)
gemm_zr(const float* __restrict__ A1, const float* __restrict__ A2,
        const float* __restrict__ B1, const float* __restrict__ B2, int n)
{
    __shared__ __half Ah[64 * AH_LD];
    __shared__ __half Bh[16 * BH_LD_ZR];
    __shared__ float Cs[64 * CS_LD_ZR];

    int tid = threadIdx.x, warp = tid >> 5;
    int warp_m = warp >> 1, warp_n = warp & 1;
    int row0 = blockIdx.x * 64;

    wmma::fragment<wmma::accumulator, 16, 16, 16, float> acc[4];
#pragma unroll
    for (int j = 0; j < 4; j++) wmma::fill_fragment(acc[j], 0.f);

    int a_row = tid >> 2;
    int a_kg = (tid & 3) * 4;
    int b_kk = tid >> 4;
    int b_q = tid & 15;

    for (int k0 = 0; k0 < D; k0 += 16) {
        {
            int grow = row0 + a_row;
            int k = k0 + a_kg;
            float4 v = make_float4(0.f, 0.f, 0.f, 0.f);
            if (grow < n) {
                if (k < FIN) v = *(const float4*)(A1 + (size_t)grow * FIN + k);
                else         v = *(const float4*)(A2 + (size_t)grow * C + (k - FIN));
            }
            __half2* pa = (__half2*)(Ah + a_row * AH_LD + a_kg);
            pa[0] = __floats2half2_rn(v.x, v.y);
            pa[1] = __floats2half2_rn(v.z, v.w);
        }
        {
            float4 vz = *(const float4*)(B1 + (size_t)(k0 + b_kk) * C + b_q * 4);
            float4 vr = *(const float4*)(B2 + (size_t)(k0 + b_kk) * C + b_q * 4);
            __half2* pb = (__half2*)(Bh + b_kk * BH_LD_ZR + b_q * 8);
            pb[0] = __floats2half2_rn(vz.x, vz.y);
            pb[1] = __floats2half2_rn(vr.x, vr.y);
            pb[2] = __floats2half2_rn(vz.z, vz.w);
            pb[3] = __floats2half2_rn(vr.z, vr.w);
        }
        __syncthreads();

        wmma::fragment<wmma::matrix_a, 16, 16, 16, __half, wmma::row_major> fa;
        wmma::load_matrix_sync(fa, Ah + warp_m * 16 * AH_LD, AH_LD);
#pragma unroll
        for (int j = 0; j < 4; j++) {
            wmma::fragment<wmma::matrix_b, 16, 16, 16, __half, wmma::row_major> fb;
            wmma::load_matrix_sync(fb, Bh + warp_n * 64 + j * 16, BH_LD_ZR);
            wmma::mma_sync(acc[j], fa, fb, acc[j]);
        }
        __syncthreads();
    }

#pragma unroll
    for (int j = 0; j < 4; j++)
        wmma::store_matrix_sync(Cs + warp_m * 16 * CS_LD_ZR + warp_n * 64 + j * 16,
                                acc[j], CS_LD_ZR, wmma::mem_row_major);
    __syncthreads();
    {
        int r = tid >> 2, c0 = (tid & 3) * 32;
        int grow = row0 + r;
        if (grow < n) {
#pragma unroll
            for (int c = 0; c < 32; c += 8) {
                float4 f0 = *(const float4*)(Cs + r * CS_LD_ZR + c0 + c);
                float4 f1 = *(const float4*)(Cs + r * CS_LD_ZR + c0 + c + 4);
                __half2 h0 = __floats2half2_rn(f0.x, f0.y);
                __half2 h1 = __floats2half2_rn(f0.z, f0.w);
                __half2 h2 = __floats2half2_rn(f1.x, f1.y);
                __half2 h3 = __floats2half2_rn(f1.z, f1.w);
                uint4 pk;
                pk.x = *(uint32_t*)&h0; pk.y = *(uint32_t*)&h1;
                pk.z = *(uint32_t*)&h2; pk.w = *(uint32_t*)&h3;
                *(uint4*)(g_hzr + (size_t)grow * 128 + c0 + c) = pk;
            }
        }
    }
}

// gemm_h: BM=64, BN=64, 8 warps as 4x2 (warp tile 16x32), A2 = g_HR (half).
__global__ void __launch_bounds__(256)
gemm_h(const float* __restrict__ A1, const float* __restrict__ B1, int n)
{
    __shared__ __half Ah[64 * AH_LD];
    __shared__ __half Bh[16 * BH_LD_H];
    __shared__ float Cs[64 * CS_LD_H];

    int tid = threadIdx.x, warp = tid >> 5;
    int warp_m = warp >> 1, warp_n = warp & 1;
    int row0 = blockIdx.x * 64;

    wmma::fragment<wmma::accumulator, 16, 16, 16, float> acc[2];
#pragma unroll
    for (int j = 0; j < 2; j++) wmma::fill_fragment(acc[j], 0.f);

    int a_row = tid >> 2;
    int a_kg = (tid & 3) * 4;
    int b_kk = tid >> 4;
    int b_col = (tid & 15) * 4;

    for (int k0 = 0; k0 < D; k0 += 16) {
        {
            int grow = row0 + a_row;
            int k = k0 + a_kg;
            __half2 p0, p1;
            if (grow < n && k < FIN) {
                float4 v = *(const float4*)(A1 + (size_t)grow * FIN + k);
                p0 = __floats2half2_rn(v.x, v.y);
                p1 = __floats2half2_rn(v.z, v.w);
            } else if (grow < n) {
                uint2 raw = *(const uint2*)(g_HR + (size_t)grow * C + (k - FIN));
                p0 = *(__half2*)&raw.x;
                p1 = *(__half2*)&raw.y;
            } else {
                p0 = __floats2half2_rn(0.f, 0.f);
                p1 = p0;
            }
            __half2* pa = (__half2*)(Ah + a_row * AH_LD + a_kg);
            pa[0] = p0; pa[1] = p1;
        }
        {
            float4 v = *(const float4*)(B1 + (size_t)(k0 + b_kk) * C + b_col);
            __half2* pb = (__half2*)(Bh + b_kk * BH_LD_H + b_col);
            pb[0] = __floats2half2_rn(v.x, v.y);
            pb[1] = __floats2half2_rn(v.z, v.w);
        }
        __syncthreads();

        wmma::fragment<wmma::matrix_a, 16, 16, 16, __half, wmma::row_major> fa;
        wmma::load_matrix_sync(fa, Ah + warp_m * 16 * AH_LD, AH_LD);
#pragma unroll
        for (int j = 0; j < 2; j++) {
            wmma::fragment<wmma::matrix_b, 16, 16, 16, __half, wmma::row_major> fb;
            wmma::load_matrix_sync(fb, Bh + warp_n * 32 + j * 16, BH_LD_H);
            wmma::mma_sync(acc[j], fa, fb, acc[j]);
        }
        __syncthreads();
    }

#pragma unroll
    for (int j = 0; j < 2; j++)
        wmma::store_matrix_sync(Cs + warp_m * 16 * CS_LD_H + warp_n * 32 + j * 16,
                                acc[j], CS_LD_H, wmma::mem_row_major);
    __syncthreads();
    {
        int r = tid >> 2, c0 = (tid & 3) * 16;
        int grow = row0 + r;
        if (grow < n) {
#pragma unroll
            for (int c = 0; c < 16; c += 8) {
                float4 f0 = *(const float4*)(Cs + r * CS_LD_H + c0 + c);
                float4 f1 = *(const float4*)(Cs + r * CS_LD_H + c0 + c + 4);
                __half2 h0 = __floats2half2_rn(f0.x, f0.y);
                __half2 h1 = __floats2half2_rn(f0.z, f0.w);
                __half2 h2 = __floats2half2_rn(f1.x, f1.y);
                __half2 h3 = __floats2half2_rn(f1.z, f1.w);
                uint4 pk;
                pk.x = *(uint32_t*)&h0; pk.y = *(uint32_t*)&h1;
                pk.z = *(uint32_t*)&h2; pk.w = *(uint32_t*)&h3;
                *(uint4*)(g_hh + (size_t)grow * C + c0 + c) = pk;
            }
        }
    }
}

// ================= attention scalars =================
__global__ void node_attn_zr(const float* __restrict__ az_s, const float* __restrict__ az_d,
                             const float* __restrict__ ar_s, const float* __restrict__ ar_d,
                             int n)
{
    int w = (blockIdx.x * blockDim.x + threadIdx.x) >> 5;
    if (w >= n) return;
    int l = threadIdx.x & 31;
    uint2 raw = *(const uint2*)(g_hzr + (size_t)w * 128 + 4 * l);
    float2 vz = __half22float2(*(__half2*)&raw.x);
    float2 vr = __half22float2(*(__half2*)&raw.y);
    float sz = vz.x * __ldg(az_s + 2 * l) + vz.y * __ldg(az_s + 2 * l + 1);
    float dz = vz.x * __ldg(az_d + 2 * l) + vz.y * __ldg(az_d + 2 * l + 1);
    float sr = vr.x * __ldg(ar_s + 2 * l) + vr.y * __ldg(ar_s + 2 * l + 1);
    float dr = vr.x * __ldg(ar_d + 2 * l) + vr.y * __ldg(ar_d + 2 * l + 1);
#pragma unroll
    for (int o = 16; o; o >>= 1) {
        sz += __shfl_xor_sync(0xffffffffu, sz, o);
        dz += __shfl_xor_sync(0xffffffffu, dz, o);
        sr += __shfl_xor_sync(0xffffffffu, sr, o);
        dr += __shfl_xor_sync(0xffffffffu, dr, o);
    }
    if (l == 0) { g_als_z[w] = sz; g_ald_z[w] = dz; g_als_r[w] = sr; g_ald_r[w] = dr; }
}

__global__ void node_attn_h(const float* __restrict__ a_src, const float* __restrict__ a_dst, int n)
{
    int w = (blockIdx.x * blockDim.x + threadIdx.x) >> 5;
    if (w >= n) return;
    int l = threadIdx.x & 31;
    float h0 = __half2float(g_hh[(size_t)w * C + l]);
    float h1 = __half2float(g_hh[(size_t)w * C + 32 + l]);
    float s = h0 * __ldg(a_src + l) + h1 * __ldg(a_src + 32 + l);
    float d = h0 * __ldg(a_dst + l) + h1 * __ldg(a_dst + 32 + l);
#pragma unroll
    for (int o = 16; o; o >>= 1) {
        s += __shfl_xor_sync(0xffffffffu, s, o);
        d += __shfl_xor_sync(0xffffffffu, d, o);
    }
    if (l == 0) { g_als_h[w] = s; g_ald_h[w] = d; }
}

// ================= fused per-dst accumulation =================
__global__ void zr_node(const float* __restrict__ H,
                        const float* __restrict__ bz, const float* __restrict__ br, int n)
{
    int d = (blockIdx.x * blockDim.x + threadIdx.x) >> 5;
    if (d >= n) return;
    int l = threadIdx.x & 31;

    float aldz = g_ald_z[d], aldr = g_ald_r[d];
    float alsz = g_als_z[d], alsr = g_als_r[d];

    float ez = 0.f, er = 0.f;
    if (l == 0)  ez = __expf(lrelu(alsz + aldz));
    if (l == 16) er = __expf(lrelu(alsr + aldr));
    ez = __shfl_sync(0xffffffffu, ez, 0);
    er = __shfl_sync(0xffffffffu, er, 16);

    uint2 raw = *(const uint2*)(g_hzr + (size_t)d * 128 + 4 * l);
    float2 vz = __half22float2(*(__half2*)&raw.x);
    float2 vr = __half22float2(*(__half2*)&raw.y);
    float az0 = vz.x * ez, az1 = vz.y * ez;
    float ar0 = vr.x * er, ar1 = vr.y * er;
    float denz = ez, denr = er;

    int b = g_rs[d], e_end = g_rs[d + 1];
    int i = b;
    for (; i + 1 < e_end; i += 2) {
        int s0 = g_csrc[i], s1 = g_csrc[i + 1];
        float t0 = 0.f, t1 = 0.f;
        if (l == 0)  t0 = __expf(lrelu(g_als_z[s0] + aldz));
        if (l == 1)  t1 = __expf(lrelu(g_als_z[s1] + aldz));
        if (l == 16) t0 = __expf(lrelu(g_als_r[s0] + aldr));
        if (l == 17) t1 = __expf(lrelu(g_als_r[s1] + aldr));
        float ez0 = __shfl_sync(0xffffffffu, t0, 0);
        float ez1 = __shfl_sync(0xffffffffu, t1, 1);
        float er0 = __shfl_sync(0xffffffffu, t0, 16);
        float er1 = __shfl_sync(0xffffffffu, t1, 17);
        uint2 r0 = *(const uint2*)(g_hzr + (size_t)s0 * 128 + 4 * l);
        uint2 r1 = *(const uint2*)(g_hzr + (size_t)s1 * 128 + 4 * l);
        float2 uz0 = __half22float2(*(__half2*)&r0.x);
        float2 ur0 = __half22float2(*(__half2*)&r0.y);
        float2 uz1 = __half22float2(*(__half2*)&r1.x);
        float2 ur1 = __half22float2(*(__half2*)&r1.y);
        az0 += uz0.x * ez0 + uz1.x * ez1;
        az1 += uz0.y * ez0 + uz1.y * ez1;
        ar0 += ur0.x * er0 + ur1.x * er1;
        ar1 += ur0.y * er0 + ur1.y * er1;
        denz += ez0 + ez1;
        denr += er0 + er1;
    }
    if (i < e_end) {
        int s0 = g_csrc[i];
        float t0 = 0.f;
        if (l == 0)  t0 = __expf(lrelu(g_als_z[s0] + aldz));
        if (l == 16) t0 = __expf(lrelu(g_als_r[s0] + aldr));
        float ez0 = __shfl_sync(0xffffffffu, t0, 0);
        float er0 = __shfl_sync(0xffffffffu, t0, 16);
        uint2 r0 = *(const uint2*)(g_hzr + (size_t)s0 * 128 + 4 * l);
        float2 uz0 = __half22float2(*(__half2*)&r0.x);
        float2 ur0 = __half22float2(*(__half2*)&r0.y);
        az0 += uz0.x * ez0; az1 += uz0.y * ez0;
        ar0 += ur0.x * er0; ar1 += ur0.y * er0;
        denz += ez0; denr += er0;
    }

    float iz = 1.f / (denz + 1e-16f), ir = 1.f / (denr + 1e-16f);
    float Z0 = sigmoidf_(az0 * iz + __ldg(bz + 2 * l));
    float Z1 = sigmoidf_(az1 * iz + __ldg(bz + 2 * l + 1));
    float R0 = sigmoidf_(ar0 * ir + __ldg(br + 2 * l));
    float R1 = sigmoidf_(ar1 * ir + __ldg(br + 2 * l + 1));
    float2 Hv = *(const float2*)(H + (size_t)d * C + 2 * l);
    *(float2*)(g_Z + (size_t)d * C + 2 * l) = make_float2(Z0, Z1);
    __half2 hr = __floats2half2_rn(Hv.x * R0, Hv.y * R1);
    *(uint32_t*)(g_HR + (size_t)d * C + 2 * l) = *(uint32_t*)&hr;
}

__global__ void h_node(const float* __restrict__ H, const float* __restrict__ bh,
                       float* __restrict__ out, int n)
{
    int d = (blockIdx.x * blockDim.x + threadIdx.x) >> 5;
    if (d >= n) return;
    int l = threadIdx.x & 31;

    float aldh = g_ald_h[d];
    float alsh = g_als_h[d];

    float eh = 0.f;
    if (l == 0) eh = __expf(lrelu(alsh + aldh));
    eh = __shfl_sync(0xffffffffu, eh, 0);

    uint32_t raw = *(const uint32_t*)(g_hh + (size_t)d * C + 2 * l);
    float2 v = __half22float2(*(__half2*)&raw);
    float a0 = v.x * eh, a1 = v.y * eh;
    float den = eh;

    int b = g_rs[d], e_end = g_rs[d + 1];
    int i = b;
    for (; i + 1 < e_end; i += 2) {
        int s0 = g_csrc[i], s1 = g_csrc[i + 1];
        float t0 = 0.f, t1 = 0.f;
        if (l == 0) t0 = __expf(lrelu(g_als_h[s0] + aldh));
        if (l == 1) t1 = __expf(lrelu(g_als_h[s1] + aldh));
        float eh0 = __shfl_sync(0xffffffffu, t0, 0);
        float eh1 = __shfl_sync(0xffffffffu, t1, 1);
        uint32_t w0 = *(const uint32_t*)(g_hh + (size_t)s0 * C + 2 * l);
        uint32_t w1 = *(const uint32_t*)(g_hh + (size_t)s1 * C + 2 * l);
        float2 u0 = __half22float2(*(__half2*)&w0);
        float2 u1 = __half22float2(*(__half2*)&w1);
        a0 += u0.x * eh0 + u1.x * eh1;
        a1 += u0.y * eh0 + u1.y * eh1;
        den += eh0 + eh1;
    }
    if (i < e_end) {
        int s0 = g_csrc[i];
        float t0 = 0.f;
        if (l == 0) t0 = __expf(lrelu(g_als_h[s0] + aldh));
        float eh0 = __shfl_sync(0xffffffffu, t0, 0);
        uint32_t w0 = *(const uint32_t*)(g_hh + (size_t)s0 * C + 2 * l);
        float2 u0 = __half22float2(*(__half2*)&w0);
        a0 += u0.x * eh0; a1 += u0.y * eh0;
        den += eh0;
    }

    float inv = 1.f / (den + 1e-16f);
    float ht0 = tanhf(a0 * inv + __ldg(bh + 2 * l));
    float ht1 = tanhf(a1 * inv + __ldg(bh + 2 * l + 1));
    float2 Zv = *(const float2*)(g_Z + (size_t)d * C + 2 * l);
    float2 Hv = *(const float2*)(H + (size_t)d * C + 2 * l);
    float o0 = Zv.x * Hv.x + (1.f - Zv.x) * ht0;
    float o1 = Zv.y * Hv.y + (1.f - Zv.y) * ht1;
    *(float2*)(out + (size_t)d * C + 2 * l) = make_float2(o0, o1);
}

// ---------------- launch: CSR build overlapped on a side stream -------------
extern "C" void kernel_launch(void* const* d_in, const int* in_sizes, int n_in,
                              void* d_out, int out_size)
{
    const float* X    = (const float*)d_in[0];
    const int*   ei   = (const int*)  d_in[1];
    const float* H    = (const float*)d_in[2];
    const float* Wz   = (const float*)d_in[3];
    const float* az_s = (const float*)d_in[4];
    const float* az_d = (const float*)d_in[5];
    const float* bz   = (const float*)d_in[6];
    const float* Wr   = (const float*)d_in[7];
    const float* ar_s = (const float*)d_in[8];
    const float* ar_d = (const float*)d_in[9];
    const float* br   = (const float*)d_in[10];
    const float* Wh   = (const float*)d_in[11];
    const float* ah_s = (const float*)d_in[12];
    const float* ah_d = (const float*)d_in[13];
    const float* bh   = (const float*)d_in[14];

    int n = in_sizes[0] / FIN;
    int E = in_sizes[1] / 2;
    const int* src = ei;
    const int* dst = ei + E;

    int nb = (n + SCAN_B - 1) / SCAN_B;
    int gemm_blocks = (n + 63) / 64;
    int warp_blocks = (n * 32 + 255) / 256;
    int eth = (E + 255) / 256;

    // Lazily create side stream + fork/join events on the first (uncaptured)
    // correctness call; reused identically on every call thereafter.
    static cudaStream_t s_side = nullptr;
    static cudaEvent_t s_fork = nullptr, s_join = nullptr;
    if (s_side == nullptr) {
        cudaStreamCreateWithFlags(&s_side, cudaStreamNonBlocking);
        cudaEventCreateWithFlags(&s_fork, cudaEventDisableTiming);
        cudaEventCreateWithFlags(&s_join, cudaEventDisableTiming);
    }

    // Fork: side stream builds the CSR while the main stream runs the z/r GEMM
    // chain. Join before zr_node (first consumer of g_rs/g_csrc).
    cudaEventRecord(s_fork, 0);
    cudaStreamWaitEvent(s_side, s_fork, 0);

    k_zero_cnt<<<(n + 255) / 256, 256, 0, s_side>>>(n);       // launch 0 (side)
    k_count<<<eth, 256, 0, s_side>>>(dst, E);                 // launch 1 (side)
    k_scan1<<<nb, SCAN_B, 0, s_side>>>(n);                    // launch 2 (side)
    gemm_zr<<<gemm_blocks, 256>>>(X, H, Wz, Wr, n);           // launch 3 (main) <- profiled
    k_scan2<<<1, 512, 0, s_side>>>(nb, n);                    // launch 4 (side)
    k_scan3<<<nb, SCAN_B, 0, s_side>>>(n);                    // launch 5 (side)
    k_scatter<<<eth, 256, 0, s_side>>>(src, dst, E);          // launch 6 (side)
    cudaEventRecord(s_join, s_side);

    node_attn_zr<<<warp_blocks, 256>>>(az_s, az_d, ar_s, ar_d, n);  // main

    cudaStreamWaitEvent(0, s_join, 0);                        // join
    zr_node<<<warp_blocks, 256>>>(H, bz, br, n);

    gemm_h<<<gemm_blocks, 256>>>(X, Wh, n);
    node_attn_h<<<warp_blocks, 256>>>(ah_s, ah_d, n);
    h_node<<<warp_blocks, 256>>>(H, bh, (float*)d_out, n);
}

// round 13
// speedup vs baseline: 1.8893x; 1.3052x over previous
#include <cuda_runtime.h>
#include <cuda_fp16.h>
#include <mma.h>
#include <cstdint>

using namespace nvcuda;

#define N_MAX 50000
#define N_PAD 50048          // ceil(N_MAX/64)*64 for unguarded fragment stores
#define E_MAX 800000
#define C 64
#define FIN 128
#define D 192
#define NEG_SLOPE 0.2f
#define SCAN_B 512

// ---------------- scratch (static __device__; no allocations allowed) -------
__device__ __align__(16) __half g_hzr[N_MAX * 128];  // interleaved: [z2p,z2p+1,r2p,r2p+1]
__device__ __align__(16) __half g_hh[N_MAX * C];
__device__ __align__(16) __half g_HR[N_MAX * C];     // H*R (half), feeds gemm_hhr
__device__ __align__(16) float g_hhp[N_PAD * C];     // X@Wh[0:128] fp32 partial
__device__ __align__(16) float g_Z[N_MAX * C];
__device__ float g_als_z[N_MAX], g_ald_z[N_MAX];
__device__ float g_als_r[N_MAX], g_ald_r[N_MAX];
__device__ float g_als_h[N_MAX], g_ald_h[N_MAX];
__device__ int g_cnt[N_MAX];
__device__ int g_rs[N_MAX + 1];
__device__ int g_cur[N_MAX];
__device__ int g_bsum[512], g_boff[512];
__device__ int g_csrc[E_MAX];        // src per CSR slot
__device__ int g_cdst[E_MAX];        // dst per CSR slot
__device__ uint32_t g_ewzr[E_MAX];   // half2 {ez, er} per CSR slot
__device__ __half g_ewh[E_MAX];      // eh per CSR slot

// ---------------- helpers ----------------
__device__ __forceinline__ float lrelu(float x) { return x > 0.f ? x : NEG_SLOPE * x; }
__device__ __forceinline__ float sigmoidf_(float x) { return 1.f / (1.f + __expf(-x)); }

// ================= CSR build =================
__global__ void k_zero_cnt(int n) {
    int i = blockIdx.x * blockDim.x + threadIdx.x;
    if (i < n) g_cnt[i] = 0;
}
__global__ void k_count(const int* __restrict__ dst, int E) {
    int e = blockIdx.x * blockDim.x + threadIdx.x;
    if (e < E) atomicAdd(&g_cnt[dst[e]], 1);
}
__global__ void k_scan1(int n) {
    __shared__ int sm[SCAN_B];
    int i = blockIdx.x * SCAN_B + threadIdx.x;
    int c = (i < n) ? g_cnt[i] : 0;
    sm[threadIdx.x] = c;
    __syncthreads();
    for (int off = SCAN_B / 2; off; off >>= 1) {
        if (threadIdx.x < off) sm[threadIdx.x] += sm[threadIdx.x + off];
        __syncthreads();
    }
    if (threadIdx.x == 0) g_bsum[blockIdx.x] = sm[0];
}
__global__ void k_scan2(int nb, int n) {
    __shared__ int sm[512];
    int t = threadIdx.x;
    int v = (t < nb) ? g_bsum[t] : 0;
    sm[t] = v;
    __syncthreads();
    for (int off = 1; off < 512; off <<= 1) {
        int u = (t >= off) ? sm[t - off] : 0;
        __syncthreads();
        sm[t] += u;
        __syncthreads();
    }
    if (t < nb) g_boff[t] = sm[t] - v;
    if (t == 511) g_rs[n] = sm[511];
}
__global__ void k_scan3(int n) {
    __shared__ int sm[SCAN_B];
    int t = threadIdx.x;
    int i = blockIdx.x * SCAN_B + t;
    int c = (i < n) ? g_cnt[i] : 0;
    sm[t] = c;
    __syncthreads();
    for (int off = 1; off < SCAN_B; off <<= 1) {
        int v = (t >= off) ? sm[t - off] : 0;
        __syncthreads();
        sm[t] += v;
        __syncthreads();
    }
    if (i < n) {
        int excl = g_boff[blockIdx.x] + sm[t] - c;
        g_rs[i] = excl;
        g_cur[i] = excl;
    }
}
__global__ void k_scatter(const int* __restrict__ src, const int* __restrict__ dst, int E) {
    int e = blockIdx.x * blockDim.x + threadIdx.x;
    if (e < E) {
        int d = dst[e];
        int pos = atomicAdd(&g_cur[d], 1);
        g_csrc[pos] = src[e];
        g_cdst[pos] = d;
    }
}

// ================= edge weights (CSR-slot-parallel) =================
__global__ void ew_zr(int E) {
    int i = blockIdx.x * blockDim.x + threadIdx.x;
    if (i >= E) return;
    int s = g_csrc[i], d = g_cdst[i];
    float ez = __expf(lrelu(g_als_z[s] + g_ald_z[d]));
    float er = __expf(lrelu(g_als_r[s] + g_ald_r[d]));
    __half2 p = __floats2half2_rn(ez, er);
    g_ewzr[i] = *(uint32_t*)&p;
}
__global__ void ew_h(int E) {
    int i = blockIdx.x * blockDim.x + threadIdx.x;
    if (i >= E) return;
    int s = g_csrc[i], d = g_cdst[i];
    g_ewh[i] = __float2half(__expf(lrelu(g_als_h[s] + g_ald_h[d])));
}

// ================= fp16 wmma GEMMs =================
#define AH_LD 24
#define BH_LD_ZR 136
#define BH_LD_H 72
#define CS_LD_ZR 132
#define CS_LD_H 68

// gemm_zr: BM=64, BN=128 (z|r interleaved pairs), 8 warps as 4x2.
__global__ void __launch_bounds__(256)
gemm_zr(const float* __restrict__ A1, const float* __restrict__ A2,
        const float* __restrict__ B1, const float* __restrict__ B2, int n)
{
    __shared__ __half Ah[64 * AH_LD];
    __shared__ __half Bh[16 * BH_LD_ZR];
    __shared__ float Cs[64 * CS_LD_ZR];

    int tid = threadIdx.x, warp = tid >> 5;
    int warp_m = warp >> 1, warp_n = warp & 1;
    int row0 = blockIdx.x * 64;

    wmma::fragment<wmma::accumulator, 16, 16, 16, float> acc[4];
#pragma unroll
    for (int j = 0; j < 4; j++) wmma::fill_fragment(acc[j], 0.f);

    int a_row = tid >> 2;
    int a_kg = (tid & 3) * 4;
    int b_kk = tid >> 4;
    int b_q = tid & 15;

    for (int k0 = 0; k0 < D; k0 += 16) {
        {
            int grow = row0 + a_row;
            int k = k0 + a_kg;
            float4 v = make_float4(0.f, 0.f, 0.f, 0.f);
            if (grow < n) {
                if (k < FIN) v = *(const float4*)(A1 + (size_t)grow * FIN + k);
                else         v = *(const float4*)(A2 + (size_t)grow * C + (k - FIN));
            }
            __half2* pa = (__half2*)(Ah + a_row * AH_LD + a_kg);
            pa[0] = __floats2half2_rn(v.x, v.y);
            pa[1] = __floats2half2_rn(v.z, v.w);
        }
        {
            float4 vz = *(const float4*)(B1 + (size_t)(k0 + b_kk) * C + b_q * 4);
            float4 vr = *(const float4*)(B2 + (size_t)(k0 + b_kk) * C + b_q * 4);
            __half2* pb = (__half2*)(Bh + b_kk * BH_LD_ZR + b_q * 8);
            pb[0] = __floats2half2_rn(vz.x, vz.y);
            pb[1] = __floats2half2_rn(vr.x, vr.y);
            pb[2] = __floats2half2_rn(vz.z, vz.w);
            pb[3] = __floats2half2_rn(vr.z, vr.w);
        }
        __syncthreads();

        wmma::fragment<wmma::matrix_a, 16, 16, 16, __half, wmma::row_major> fa;
        wmma::load_matrix_sync(fa, Ah + warp_m * 16 * AH_LD, AH_LD);
#pragma unroll
        for (int j = 0; j < 4; j++) {
            wmma::fragment<wmma::matrix_b, 16, 16, 16, __half, wmma::row_major> fb;
            wmma::load_matrix_sync(fb, Bh + warp_n * 64 + j * 16, BH_LD_ZR);
            wmma::mma_sync(acc[j], fa, fb, acc[j]);
        }
        __syncthreads();
    }

#pragma unroll
    for (int j = 0; j < 4; j++)
        wmma::store_matrix_sync(Cs + warp_m * 16 * CS_LD_ZR + warp_n * 64 + j * 16,
                                acc[j], CS_LD_ZR, wmma::mem_row_major);
    __syncthreads();
    {
        int r = tid >> 2, c0 = (tid & 3) * 32;
        int grow = row0 + r;
        if (grow < n) {
#pragma unroll
            for (int c = 0; c < 32; c += 8) {
                float4 f0 = *(const float4*)(Cs + r * CS_LD_ZR + c0 + c);
                float4 f1 = *(const float4*)(Cs + r * CS_LD_ZR + c0 + c + 4);
                __half2 h0 = __floats2half2_rn(f0.x, f0.y);
                __half2 h1 = __floats2half2_rn(f0.z, f0.w);
                __half2 h2 = __floats2half2_rn(f1.x, f1.y);
                __half2 h3 = __floats2half2_rn(f1.z, f1.w);
                uint4 pk;
                pk.x = *(uint32_t*)&h0; pk.y = *(uint32_t*)&h1;
                pk.z = *(uint32_t*)&h2; pk.w = *(uint32_t*)&h3;
                *(uint4*)(g_hzr + (size_t)grow * 128 + c0 + c) = pk;
            }
        }
    }
}

// gemm_hx: X (n x 128) @ Wh[0:128] -> fp32 partial g_hhp. Fully overlappable.
__global__ void __launch_bounds__(256)
gemm_hx(const float* __restrict__ A1, const float* __restrict__ B1, int n)
{
    __shared__ __half Ah[64 * AH_LD];
    __shared__ __half Bh[16 * BH_LD_H];

    int tid = threadIdx.x, warp = tid >> 5;
    int warp_m = warp >> 1, warp_n = warp & 1;
    int row0 = blockIdx.x * 64;

    wmma::fragment<wmma::accumulator, 16, 16, 16, float> acc[2];
#pragma unroll
    for (int j = 0; j < 2; j++) wmma::fill_fragment(acc[j], 0.f);

    int a_row = tid >> 2;
    int a_kg = (tid & 3) * 4;
    int b_kk = tid >> 4;
    int b_col = (tid & 15) * 4;

    for (int k0 = 0; k0 < FIN; k0 += 16) {
        {
            int grow = row0 + a_row;
            float4 v = make_float4(0.f, 0.f, 0.f, 0.f);
            if (grow < n) v = *(const float4*)(A1 + (size_t)grow * FIN + k0 + a_kg);
            __half2* pa = (__half2*)(Ah + a_row * AH_LD + a_kg);
            pa[0] = __floats2half2_rn(v.x, v.y);
            pa[1] = __floats2half2_rn(v.z, v.w);
        }
        {
            float4 v = *(const float4*)(B1 + (size_t)(k0 + b_kk) * C + b_col);
            __half2* pb = (__half2*)(Bh + b_kk * BH_LD_H + b_col);
            pb[0] = __floats2half2_rn(v.x, v.y);
            pb[1] = __floats2half2_rn(v.z, v.w);
        }
        __syncthreads();

        wmma::fragment<wmma::matrix_a, 16, 16, 16, __half, wmma::row_major> fa;
        wmma::load_matrix_sync(fa, Ah + warp_m * 16 * AH_LD, AH_LD);
#pragma unroll
        for (int j = 0; j < 2; j++) {
            wmma::fragment<wmma::matrix_b, 16, 16, 16, __half, wmma::row_major> fb;
            wmma::load_matrix_sync(fb, Bh + warp_n * 32 + j * 16, BH_LD_H);
            wmma::mma_sync(acc[j], fa, fb, acc[j]);
        }
        __syncthreads();
    }
    // direct fp32 store to padded partial buffer (rows >= n are don't-care)
#pragma unroll
    for (int j = 0; j < 2; j++)
        wmma::store_matrix_sync(g_hhp + (size_t)(row0 + warp_m * 16) * C + warp_n * 32 + j * 16,
                                acc[j], C, wmma::mem_row_major);
}

// gemm_hhr: g_HR (half, n x 64) @ Wh[128:192] + g_hhp -> g_hh (half). K=64 only.
__global__ void __launch_bounds__(256)
gemm_hhr(const float* __restrict__ B1, int n)
{
    __shared__ __half Ah[64 * AH_LD];
    __shared__ __half Bh[16 * BH_LD_H];
    __shared__ float Cs[64 * CS_LD_H];

    int tid = threadIdx.x, warp = tid >> 5;
    int warp_m = warp >> 1, warp_n = warp & 1;
    int row0 = blockIdx.x * 64;

    wmma::fragment<wmma::accumulator, 16, 16, 16, float> acc[2];
#pragma unroll
    for (int j = 0; j < 2; j++) wmma::fill_fragment(acc[j], 0.f);

    int a_row = tid >> 2;
    int a_kg = (tid & 3) * 4;
    int b_kk = tid >> 4;
    int b_col = (tid & 15) * 4;

    for (int k0 = 0; k0 < C; k0 += 16) {
        {
            int grow = row0 + a_row;
            uint2 raw = make_uint2(0u, 0u);
            if (grow < n) raw = *(const uint2*)(g_HR + (size_t)grow * C + k0 + a_kg);
            __half2* pa = (__half2*)(Ah + a_row * AH_LD + a_kg);
            pa[0] = *(__half2*)&raw.x;
            pa[1] = *(__half2*)&raw.y;
        }
        {
            float4 v = *(const float4*)(B1 + (size_t)(FIN + k0 + b_kk) * C + b_col);
            __half2* pb = (__half2*)(Bh + b_kk * BH_LD_H + b_col);
            pb[0] = __floats2half2_rn(v.x, v.y);
            pb[1] = __floats2half2_rn(v.z, v.w);
        }
        __syncthreads();

        wmma::fragment<wmma::matrix_a, 16, 16, 16, __half, wmma::row_major> fa;
        wmma::load_matrix_sync(fa, Ah + warp_m * 16 * AH_LD, AH_LD);
#pragma unroll
        for (int j = 0; j < 2; j++) {
            wmma::fragment<wmma::matrix_b, 16, 16, 16, __half, wmma::row_major> fb;
            wmma::load_matrix_sync(fb, Bh + warp_n * 32 + j * 16, BH_LD_H);
            wmma::mma_sync(acc[j], fa, fb, acc[j]);
        }
        __syncthreads();
    }

#pragma unroll
    for (int j = 0; j < 2; j++)
        wmma::store_matrix_sync(Cs + warp_m * 16 * CS_LD_H + warp_n * 32 + j * 16,
                                acc[j], CS_LD_H, wmma::mem_row_major);
    __syncthreads();
    {
        int r = tid >> 2, c0 = (tid & 3) * 16;
        int grow = row0 + r;
        if (grow < n) {
#pragma unroll
            for (int c = 0; c < 16; c += 8) {
                float4 f0 = *(const float4*)(Cs + r * CS_LD_H + c0 + c);
                float4 f1 = *(const float4*)(Cs + r * CS_LD_H + c0 + c + 4);
                float4 p0 = *(const float4*)(g_hhp + (size_t)grow * C + c0 + c);
                float4 p1 = *(const float4*)(g_hhp + (size_t)grow * C + c0 + c + 4);
                __half2 h0 = __floats2half2_rn(f0.x + p0.x, f0.y + p0.y);
                __half2 h1 = __floats2half2_rn(f0.z + p0.z, f0.w + p0.w);
                __half2 h2 = __floats2half2_rn(f1.x + p1.x, f1.y + p1.y);
                __half2 h3 = __floats2half2_rn(f1.z + p1.z, f1.w + p1.w);
                uint4 pk;
                pk.x = *(uint32_t*)&h0; pk.y = *(uint32_t*)&h1;
                pk.z = *(uint32_t*)&h2; pk.w = *(uint32_t*)&h3;
                *(uint4*)(g_hh + (size_t)grow * C + c0 + c) = pk;
            }
        }
    }
}

// ================= attention scalars =================
__global__ void node_attn_zr(const float* __restrict__ az_s, const float* __restrict__ az_d,
                             const float* __restrict__ ar_s, const float* __restrict__ ar_d,
                             int n)
{
    int w = (blockIdx.x * blockDim.x + threadIdx.x) >> 5;
    if (w >= n) return;
    int l = threadIdx.x & 31;
    uint2 raw = *(const uint2*)(g_hzr + (size_t)w * 128 + 4 * l);
    float2 vz = __half22float2(*(__half2*)&raw.x);
    float2 vr = __half22float2(*(__half2*)&raw.y);
    float sz = vz.x * __ldg(az_s + 2 * l) + vz.y * __ldg(az_s + 2 * l + 1);
    float dz = vz.x * __ldg(az_d + 2 * l) + vz.y * __ldg(az_d + 2 * l + 1);
    float sr = vr.x * __ldg(ar_s + 2 * l) + vr.y * __ldg(ar_s + 2 * l + 1);
    float dr = vr.x * __ldg(ar_d + 2 * l) + vr.y * __ldg(ar_d + 2 * l + 1);
#pragma unroll
    for (int o = 16; o; o >>= 1) {
        sz += __shfl_xor_sync(0xffffffffu, sz, o);
        dz += __shfl_xor_sync(0xffffffffu, dz, o);
        sr += __shfl_xor_sync(0xffffffffu, sr, o);
        dr += __shfl_xor_sync(0xffffffffu, dr, o);
    }
    if (l == 0) { g_als_z[w] = sz; g_ald_z[w] = dz; g_als_r[w] = sr; g_ald_r[w] = dr; }
}

__global__ void node_attn_h(const float* __restrict__ a_src, const float* __restrict__ a_dst, int n)
{
    int w = (blockIdx.x * blockDim.x + threadIdx.x) >> 5;
    if (w >= n) return;
    int l = threadIdx.x & 31;
    float h0 = __half2float(g_hh[(size_t)w * C + l]);
    float h1 = __half2float(g_hh[(size_t)w * C + 32 + l]);
    float s = h0 * __ldg(a_src + l) + h1 * __ldg(a_src + 32 + l);
    float d = h0 * __ldg(a_dst + l) + h1 * __ldg(a_dst + 32 + l);
#pragma unroll
    for (int o = 16; o; o >>= 1) {
        s += __shfl_xor_sync(0xffffffffu, s, o);
        d += __shfl_xor_sync(0xffffffffu, d, o);
    }
    if (l == 0) { g_als_h[w] = s; g_ald_h[w] = d; }
}

// ================= fused per-dst accumulation (precomputed weights) =========
__global__ void zr_node(const float* __restrict__ H,
                        const float* __restrict__ bz, const float* __restrict__ br, int n)
{
    int d = (blockIdx.x * blockDim.x + threadIdx.x) >> 5;
    if (d >= n) return;
    int l = threadIdx.x & 31;

    // self-loop weight (one exp per gate per node, inline)
    float ez = 0.f, er = 0.f;
    if (l == 0)  ez = __expf(lrelu(g_als_z[d] + g_ald_z[d]));
    if (l == 16) er = __expf(lrelu(g_als_r[d] + g_ald_r[d]));
    ez = __shfl_sync(0xffffffffu, ez, 0);
    er = __shfl_sync(0xffffffffu, er, 16);

    uint2 raw = *(const uint2*)(g_hzr + (size_t)d * 128 + 4 * l);
    float2 vz = __half22float2(*(__half2*)&raw.x);
    float2 vr = __half22float2(*(__half2*)&raw.y);
    float az0 = vz.x * ez, az1 = vz.y * ez;
    float ar0 = vr.x * er, ar1 = vr.y * er;
    float denz = ez, denr = er;

    int b = g_rs[d], e_end = g_rs[d + 1];
    int i = b;
    for (; i + 1 < e_end; i += 2) {
        int s0 = g_csrc[i], s1 = g_csrc[i + 1];
        uint32_t w0 = g_ewzr[i], w1 = g_ewzr[i + 1];
        float2 e0 = __half22float2(*(__half2*)&w0);
        float2 e1 = __half22float2(*(__half2*)&w1);
        uint2 r0 = *(const uint2*)(g_hzr + (size_t)s0 * 128 + 4 * l);
        uint2 r1 = *(const uint2*)(g_hzr + (size_t)s1 * 128 + 4 * l);
        float2 uz0 = __half22float2(*(__half2*)&r0.x);
        float2 ur0 = __half22float2(*(__half2*)&r0.y);
        float2 uz1 = __half22float2(*(__half2*)&r1.x);
        float2 ur1 = __half22float2(*(__half2*)&r1.y);
        az0 += uz0.x * e0.x + uz1.x * e1.x;
        az1 += uz0.y * e0.x + uz1.y * e1.x;
        ar0 += ur0.x * e0.y + ur1.x * e1.y;
        ar1 += ur0.y * e0.y + ur1.y * e1.y;
        denz += e0.x + e1.x;
        denr += e0.y + e1.y;
    }
    if (i < e_end) {
        int s0 = g_csrc[i];
        uint32_t w0 = g_ewzr[i];
        float2 e0 = __half22float2(*(__half2*)&w0);
        uint2 r0 = *(const uint2*)(g_hzr + (size_t)s0 * 128 + 4 * l);
        float2 uz0 = __half22float2(*(__half2*)&r0.x);
        float2 ur0 = __half22float2(*(__half2*)&r0.y);
        az0 += uz0.x * e0.x; az1 += uz0.y * e0.x;
        ar0 += ur0.x * e0.y; ar1 += ur0.y * e0.y;
        denz += e0.x; denr += e0.y;
    }

    float iz = 1.f / (denz + 1e-16f), ir = 1.f / (denr + 1e-16f);
    float Z0 = sigmoidf_(az0 * iz + __ldg(bz + 2 * l));
    float Z1 = sigmoidf_(az1 * iz + __ldg(bz + 2 * l + 1));
    float R0 = sigmoidf_(ar0 * ir + __ldg(br + 2 * l));
    float R1 = sigmoidf_(ar1 * ir + __ldg(br + 2 * l + 1));
    float2 Hv = *(const float2*)(H + (size_t)d * C + 2 * l);
    *(float2*)(g_Z + (size_t)d * C + 2 * l) = make_float2(Z0, Z1);
    __half2 hr = __floats2half2_rn(Hv.x * R0, Hv.y * R1);
    *(uint32_t*)(g_HR + (size_t)d * C + 2 * l) = *(uint32_t*)&hr;
}

__global__ void h_node(const float* __restrict__ H, const float* __restrict__ bh,
                       float* __restrict__ out, int n)
{
    int d = (blockIdx.x * blockDim.x + threadIdx.x) >> 5;
    if (d >= n) return;
    int l = threadIdx.x & 31;

    float eh = 0.f;
    if (l == 0) eh = __expf(lrelu(g_als_h[d] + g_ald_h[d]));
    eh = __shfl_sync(0xffffffffu, eh, 0);

    uint32_t raw = *(const uint32_t*)(g_hh + (size_t)d * C + 2 * l);
    float2 v = __half22float2(*(__half2*)&raw);
    float a0 = v.x * eh, a1 = v.y * eh;
    float den = eh;

    int b = g_rs[d], e_end = g_rs[d + 1];
    int i = b;
    for (; i + 1 < e_end; i += 2) {
        int s0 = g_csrc[i], s1 = g_csrc[i + 1];
        float eh0 = __half2float(g_ewh[i]);
        float eh1 = __half2float(g_ewh[i + 1]);
        uint32_t w0 = *(const uint32_t*)(g_hh + (size_t)s0 * C + 2 * l);
        uint32_t w1 = *(const uint32_t*)(g_hh + (size_t)s1 * C + 2 * l);
        float2 u0 = __half22float2(*(__half2*)&w0);
        float2 u1 = __half22float2(*(__half2*)&w1);
        a0 += u0.x * eh0 + u1.x * eh1;
        a1 += u0.y * eh0 + u1.y * eh1;
        den += eh0 + eh1;
    }
    if (i < e_end) {
        int s0 = g_csrc[i];
        float eh0 = __half2float(g_ewh[i]);
        uint32_t w0 = *(const uint32_t*)(g_hh + (size_t)s0 * C + 2 * l);
        float2 u0 = __half22float2(*(__half2*)&w0);
        a0 += u0.x * eh0; a1 += u0.y * eh0;
        den += eh0;
    }

    float inv = 1.f / (den + 1e-16f);
    float ht0 = tanhf(a0 * inv + __ldg(bh + 2 * l));
    float ht1 = tanhf(a1 * inv + __ldg(bh + 2 * l + 1));
    float2 Zv = *(const float2*)(g_Z + (size_t)d * C + 2 * l);
    float2 Hv = *(const float2*)(H + (size_t)d * C + 2 * l);
    float o0 = Zv.x * Hv.x + (1.f - Zv.x) * ht0;
    float o1 = Zv.y * Hv.y + (1.f - Zv.y) * ht1;
    *(float2*)(out + (size_t)d * C + 2 * l) = make_float2(o0, o1);
}

// ---------------- launch: CSR + X@Wh overlapped on a side stream ------------
extern "C" void kernel_launch(void* const* d_in, const int* in_sizes, int n_in,
                              void* d_out, int out_size)
{
    const float* X    = (const float*)d_in[0];
    const int*   ei   = (const int*)  d_in[1];
    const float* H    = (const float*)d_in[2];
    const float* Wz   = (const float*)d_in[3];
    const float* az_s = (const float*)d_in[4];
    const float* az_d = (const float*)d_in[5];
    const float* bz   = (const float*)d_in[6];
    const float* Wr   = (const float*)d_in[7];
    const float* ar_s = (const float*)d_in[8];
    const float* ar_d = (const float*)d_in[9];
    const float* br   = (const float*)d_in[10];
    const float* Wh   = (const float*)d_in[11];
    const float* ah_s = (const float*)d_in[12];
    const float* ah_d = (const float*)d_in[13];
    const float* bh   = (const float*)d_in[14];

    int n = in_sizes[0] / FIN;
    int E = in_sizes[1] / 2;
    const int* src = ei;
    const int* dst = ei + E;

    int nb = (n + SCAN_B - 1) / SCAN_B;
    int gemm_blocks = (n + 63) / 64;
    int warp_blocks = (n * 32 + 255) / 256;
    int eth = (E + 255) / 256;

    static cudaStream_t s_side = nullptr;
    static cudaEvent_t s_fork = nullptr, s_csr = nullptr, s_hx = nullptr;
    if (s_side == nullptr) {
        cudaStreamCreateWithFlags(&s_side, cudaStreamNonBlocking);
        cudaEventCreateWithFlags(&s_fork, cudaEventDisableTiming);
        cudaEventCreateWithFlags(&s_csr, cudaEventDisableTiming);
        cudaEventCreateWithFlags(&s_hx, cudaEventDisableTiming);
    }

    cudaEventRecord(s_fork, 0);
    cudaStreamWaitEvent(s_side, s_fork, 0);

    // side: CSR build, then the independent X@Wh partial GEMM
    k_zero_cnt<<<(n + 255) / 256, 256, 0, s_side>>>(n);       // 0 (side)
    k_count<<<eth, 256, 0, s_side>>>(dst, E);                 // 1 (side)
    k_scan1<<<nb, SCAN_B, 0, s_side>>>(n);                    // 2 (side)
    gemm_zr<<<gemm_blocks, 256>>>(X, H, Wz, Wr, n);           // 3 (main) <- profiled
    k_scan2<<<1, 512, 0, s_side>>>(nb, n);                    // 4 (side)
    k_scan3<<<nb, SCAN_B, 0, s_side>>>(n);                    // 5 (side)
    k_scatter<<<eth, 256, 0, s_side>>>(src, dst, E);          // 6 (side)
    cudaEventRecord(s_csr, s_side);
    gemm_hx<<<gemm_blocks, 256, 0, s_side>>>(X, Wh, n);       // 7 (side)
    cudaEventRecord(s_hx, s_side);

    node_attn_zr<<<warp_blocks, 256>>>(az_s, az_d, ar_s, ar_d, n);  // main

    cudaStreamWaitEvent(0, s_csr, 0);                         // need CSR
    ew_zr<<<eth, 256>>>(E);
    zr_node<<<warp_blocks, 256>>>(H, bz, br, n);

    cudaStreamWaitEvent(0, s_hx, 0);                          // need X@Wh partial
    gemm_hhr<<<gemm_blocks, 256>>>(Wh, n);
    node_attn_h<<<warp_blocks, 256>>>(ah_s, ah_d, n);
    ew_h<<<eth, 256>>>(E);
    h_node<<<warp_blocks, 256>>>(H, bh, (float*)d_out, n);
}

// round 14
// speedup vs baseline: 2.0094x; 1.0636x over previous
#include <cuda_runtime.h>
#include <cuda_fp16.h>
#include <mma.h>
#include <cstdint>

using namespace nvcuda;

#define N_MAX 50000
#define N_PAD 50048
#define E_MAX 800000
#define C 64
#define FIN 128
#define D 192
#define NEG_SLOPE 0.2f
#define SCAN_B 512

// ---------------- scratch (static __device__; no allocations allowed) -------
__device__ __align__(16) __half g_hzr[N_MAX * 128];  // interleaved: [z2p,z2p+1,r2p,r2p+1]
__device__ __align__(16) __half g_hh[N_MAX * C];
__device__ __align__(16) __half g_HR[N_MAX * C];
__device__ __align__(16) float g_hhp[N_PAD * C];     // X@Wh[0:128] fp32 partial
__device__ __align__(16) float g_Z[N_MAX * C];
__device__ float g_als_z[N_MAX], g_ald_z[N_MAX];
__device__ float g_als_r[N_MAX], g_ald_r[N_MAX];
__device__ float g_als_h[N_MAX], g_ald_h[N_MAX];
__device__ int g_cnt[N_MAX];
__device__ int g_rs[N_MAX + 1];
__device__ int g_cur[N_MAX];
__device__ int g_bsum[512], g_boff[512];
__device__ int g_csrc[E_MAX];
__device__ int g_cdst[E_MAX];
__device__ uint32_t g_ewzr[E_MAX];   // half2 {ez, er}
__device__ __half g_ewh[E_MAX];

// ---------------- helpers ----------------
__device__ __forceinline__ float lrelu(float x) { return x > 0.f ? x : NEG_SLOPE * x; }
__device__ __forceinline__ float sigmoidf_(float x) { return 1.f / (1.f + __expf(-x)); }

// ================= CSR build =================
__global__ void k_zero_cnt(int n) {
    int i = blockIdx.x * blockDim.x + threadIdx.x;
    if (i < n) g_cnt[i] = 0;
}
__global__ void k_count(const int* __restrict__ dst, int E) {
    int e = blockIdx.x * blockDim.x + threadIdx.x;
    if (e < E) atomicAdd(&g_cnt[dst[e]], 1);
}
__global__ void k_scan1(int n) {
    __shared__ int sm[SCAN_B];
    int i = blockIdx.x * SCAN_B + threadIdx.x;
    int c = (i < n) ? g_cnt[i] : 0;
    sm[threadIdx.x] = c;
    __syncthreads();
    for (int off = SCAN_B / 2; off; off >>= 1) {
        if (threadIdx.x < off) sm[threadIdx.x] += sm[threadIdx.x + off];
        __syncthreads();
    }
    if (threadIdx.x == 0) g_bsum[blockIdx.x] = sm[0];
}
__global__ void k_scan2(int nb, int n) {
    __shared__ int sm[512];
    int t = threadIdx.x;
    int v = (t < nb) ? g_bsum[t] : 0;
    sm[t] = v;
    __syncthreads();
    for (int off = 1; off < 512; off <<= 1) {
        int u = (t >= off) ? sm[t - off] : 0;
        __syncthreads();
        sm[t] += u;
        __syncthreads();
    }
    if (t < nb) g_boff[t] = sm[t] - v;
    if (t == 511) g_rs[n] = sm[511];
}
__global__ void k_scan3(int n) {
    __shared__ int sm[SCAN_B];
    int t = threadIdx.x;
    int i = blockIdx.x * SCAN_B + t;
    int c = (i < n) ? g_cnt[i] : 0;
    sm[t] = c;
    __syncthreads();
    for (int off = 1; off < SCAN_B; off <<= 1) {
        int v = (t >= off) ? sm[t - off] : 0;
        __syncthreads();
        sm[t] += v;
        __syncthreads();
    }
    if (i < n) {
        int excl = g_boff[blockIdx.x] + sm[t] - c;
        g_rs[i] = excl;
        g_cur[i] = excl;
    }
}
__global__ void k_scatter(const int* __restrict__ src, const int* __restrict__ dst, int E) {
    int e = blockIdx.x * blockDim.x + threadIdx.x;
    if (e < E) {
        int d = dst[e];
        int pos = atomicAdd(&g_cur[d], 1);
        g_csrc[pos] = src[e];
        g_cdst[pos] = d;
    }
}

// ================= edge weights (CSR-slot-parallel) =================
__global__ void ew_zr(int E) {
    int i = blockIdx.x * blockDim.x + threadIdx.x;
    if (i >= E) return;
    int s = g_csrc[i], d = g_cdst[i];
    float ez = __expf(lrelu(g_als_z[s] + g_ald_z[d]));
    float er = __expf(lrelu(g_als_r[s] + g_ald_r[d]));
    __half2 p = __floats2half2_rn(ez, er);
    g_ewzr[i] = *(uint32_t*)&p;
}
__global__ void ew_h(int E) {
    int i = blockIdx.x * blockDim.x + threadIdx.x;
    if (i >= E) return;
    int s = g_csrc[i], d = g_cdst[i];
    g_ewh[i] = __float2half(__expf(lrelu(g_als_h[s] + g_ald_h[d])));
}

// ================= fp16 wmma GEMMs =================
#define AH_LD 24
#define BH_LD_ZR 136
#define BH_LD_H 72
#define CS_LD_ZR 132
#define CS_LD_H 68

// gemm_zr: BM=64, BN=128 (z|r interleaved pairs); software-pipelined gmem loads;
// epilogue computes als/ald for z and r (fused node_attn_zr).
__global__ void __launch_bounds__(256)
gemm_zr(const float* __restrict__ A1, const float* __restrict__ A2,
        const float* __restrict__ B1, const float* __restrict__ B2,
        const float* __restrict__ az_s, const float* __restrict__ az_d,
        const float* __restrict__ ar_s, const float* __restrict__ ar_d, int n)
{
    __shared__ __half Ah[64 * AH_LD];
    __shared__ __half Bh[16 * BH_LD_ZR];
    __shared__ float Cs[64 * CS_LD_ZR];

    int tid = threadIdx.x, warp = tid >> 5;
    int warp_m = warp >> 1, warp_n = warp & 1;
    int row0 = blockIdx.x * 64;

    wmma::fragment<wmma::accumulator, 16, 16, 16, float> acc[4];
#pragma unroll
    for (int j = 0; j < 4; j++) wmma::fill_fragment(acc[j], 0.f);

    int a_row = tid >> 2;
    int a_kg = (tid & 3) * 4;
    int b_kk = tid >> 4;
    int b_q = tid & 15;
    int grow = row0 + a_row;

    float4 pa, pbz, pbr;

#define LOADT(K0)                                                              \
    {                                                                          \
        int k = (K0) + a_kg;                                                   \
        pa = make_float4(0.f, 0.f, 0.f, 0.f);                                  \
        if (grow < n) {                                                        \
            if (k < FIN) pa = *(const float4*)(A1 + (size_t)grow * FIN + k);   \
            else         pa = *(const float4*)(A2 + (size_t)grow * C + (k - FIN)); \
        }                                                                      \
        pbz = *(const float4*)(B1 + (size_t)((K0) + b_kk) * C + b_q * 4);      \
        pbr = *(const float4*)(B2 + (size_t)((K0) + b_kk) * C + b_q * 4);      \
    }
#define STORET()                                                               \
    {                                                                          \
        __half2* pap = (__half2*)(Ah + a_row * AH_LD + a_kg);                  \
        pap[0] = __floats2half2_rn(pa.x, pa.y);                                \
        pap[1] = __floats2half2_rn(pa.z, pa.w);                                \
        __half2* pbp = (__half2*)(Bh + b_kk * BH_LD_ZR + b_q * 8);             \
        pbp[0] = __floats2half2_rn(pbz.x, pbz.y);                              \
        pbp[1] = __floats2half2_rn(pbr.x, pbr.y);                              \
        pbp[2] = __floats2half2_rn(pbz.z, pbz.w);                              \
        pbp[3] = __floats2half2_rn(pbr.z, pbr.w);                              \
    }

    LOADT(0);
    STORET();
    __syncthreads();

    const int nIt = D / 16;  // 12
    for (int it = 0; it < nIt; it++) {
        if (it + 1 < nIt) LOADT((it + 1) * 16);

        wmma::fragment<wmma::matrix_a, 16, 16, 16, __half, wmma::row_major> fa;
        wmma::load_matrix_sync(fa, Ah + warp_m * 16 * AH_LD, AH_LD);
#pragma unroll
        for (int j = 0; j < 4; j++) {
            wmma::fragment<wmma::matrix_b, 16, 16, 16, __half, wmma::row_major> fb;
            wmma::load_matrix_sync(fb, Bh + warp_n * 64 + j * 16, BH_LD_ZR);
            wmma::mma_sync(acc[j], fa, fb, acc[j]);
        }
        __syncthreads();
        if (it + 1 < nIt) {
            STORET();
            __syncthreads();
        }
    }
#undef LOADT
#undef STORET

#pragma unroll
    for (int j = 0; j < 4; j++)
        wmma::store_matrix_sync(Cs + warp_m * 16 * CS_LD_ZR + warp_n * 64 + j * 16,
                                acc[j], CS_LD_ZR, wmma::mem_row_major);
    __syncthreads();
    {
        int r = tid >> 2;
        int grow2 = row0 + r;
        float sz = 0.f, dz = 0.f, sr = 0.f, dr = 0.f;
#pragma unroll
        for (int qq = 0; qq < 4; qq++) {
            int q = (tid & 3) * 4 + qq;          // q-group: phys cols 8q..8q+7
            float4 f0 = *(const float4*)(Cs + r * CS_LD_ZR + 8 * q);
            float4 f1 = *(const float4*)(Cs + r * CS_LD_ZR + 8 * q + 4);
            // z cols 4q..4q+3 = f0.x,f0.y,f1.x,f1.y ; r cols = f0.z,f0.w,f1.z,f1.w
            sz += f0.x * __ldg(az_s + 4 * q) + f0.y * __ldg(az_s + 4 * q + 1)
                + f1.x * __ldg(az_s + 4 * q + 2) + f1.y * __ldg(az_s + 4 * q + 3);
            dz += f0.x * __ldg(az_d + 4 * q) + f0.y * __ldg(az_d + 4 * q + 1)
                + f1.x * __ldg(az_d + 4 * q + 2) + f1.y * __ldg(az_d + 4 * q + 3);
            sr += f0.z * __ldg(ar_s + 4 * q) + f0.w * __ldg(ar_s + 4 * q + 1)
                + f1.z * __ldg(ar_s + 4 * q + 2) + f1.w * __ldg(ar_s + 4 * q + 3);
            dr += f0.z * __ldg(ar_d + 4 * q) + f0.w * __ldg(ar_d + 4 * q + 1)
                + f1.z * __ldg(ar_d + 4 * q + 2) + f1.w * __ldg(ar_d + 4 * q + 3);
            if (grow2 < n) {
                __half2 h0 = __floats2half2_rn(f0.x, f0.y);
                __half2 h1 = __floats2half2_rn(f0.z, f0.w);
                __half2 h2 = __floats2half2_rn(f1.x, f1.y);
                __half2 h3 = __floats2half2_rn(f1.z, f1.w);
                uint4 pk;
                pk.x = *(uint32_t*)&h0; pk.y = *(uint32_t*)&h1;
                pk.z = *(uint32_t*)&h2; pk.w = *(uint32_t*)&h3;
                *(uint4*)(g_hzr + (size_t)grow2 * 128 + 8 * q) = pk;
            }
        }
        // reduce across the 4 threads of this row (consecutive lanes)
        sz += __shfl_xor_sync(0xffffffffu, sz, 1);
        sz += __shfl_xor_sync(0xffffffffu, sz, 2);
        dz += __shfl_xor_sync(0xffffffffu, dz, 1);
        dz += __shfl_xor_sync(0xffffffffu, dz, 2);
        sr += __shfl_xor_sync(0xffffffffu, sr, 1);
        sr += __shfl_xor_sync(0xffffffffu, sr, 2);
        dr += __shfl_xor_sync(0xffffffffu, dr, 1);
        dr += __shfl_xor_sync(0xffffffffu, dr, 2);
        if ((tid & 3) == 0 && grow2 < n) {
            g_als_z[grow2] = sz; g_ald_z[grow2] = dz;
            g_als_r[grow2] = sr; g_ald_r[grow2] = dr;
        }
    }
}

// gemm_hx: X (n x 128) @ Wh[0:128] -> fp32 partial g_hhp (side stream).
__global__ void __launch_bounds__(256)
gemm_hx(const float* __restrict__ A1, const float* __restrict__ B1, int n)
{
    __shared__ __half Ah[64 * AH_LD];
    __shared__ __half Bh[16 * BH_LD_H];

    int tid = threadIdx.x, warp = tid >> 5;
    int warp_m = warp >> 1, warp_n = warp & 1;
    int row0 = blockIdx.x * 64;

    wmma::fragment<wmma::accumulator, 16, 16, 16, float> acc[2];
#pragma unroll
    for (int j = 0; j < 2; j++) wmma::fill_fragment(acc[j], 0.f);

    int a_row = tid >> 2;
    int a_kg = (tid & 3) * 4;
    int b_kk = tid >> 4;
    int b_col = (tid & 15) * 4;
    int grow = row0 + a_row;

    for (int k0 = 0; k0 < FIN; k0 += 16) {
        {
            float4 v = make_float4(0.f, 0.f, 0.f, 0.f);
            if (grow < n) v = *(const float4*)(A1 + (size_t)grow * FIN + k0 + a_kg);
            __half2* pa = (__half2*)(Ah + a_row * AH_LD + a_kg);
            pa[0] = __floats2half2_rn(v.x, v.y);
            pa[1] = __floats2half2_rn(v.z, v.w);
        }
        {
            float4 v = *(const float4*)(B1 + (size_t)(k0 + b_kk) * C + b_col);
            __half2* pb = (__half2*)(Bh + b_kk * BH_LD_H + b_col);
            pb[0] = __floats2half2_rn(v.x, v.y);
            pb[1] = __floats2half2_rn(v.z, v.w);
        }
        __syncthreads();

        wmma::fragment<wmma::matrix_a, 16, 16, 16, __half, wmma::row_major> fa;
        wmma::load_matrix_sync(fa, Ah + warp_m * 16 * AH_LD, AH_LD);
#pragma unroll
        for (int j = 0; j < 2; j++) {
            wmma::fragment<wmma::matrix_b, 16, 16, 16, __half, wmma::row_major> fb;
            wmma::load_matrix_sync(fb, Bh + warp_n * 32 + j * 16, BH_LD_H);
            wmma::mma_sync(acc[j], fa, fb, acc[j]);
        }
        __syncthreads();
    }
#pragma unroll
    for (int j = 0; j < 2; j++)
        wmma::store_matrix_sync(g_hhp + (size_t)(row0 + warp_m * 16) * C + warp_n * 32 + j * 16,
                                acc[j], C, wmma::mem_row_major);
}

// gemm_hhr: g_HR @ Wh[128:192] + g_hhp -> g_hh; epilogue computes als_h/ald_h.
__global__ void __launch_bounds__(256)
gemm_hhr(const float* __restrict__ B1,
         const float* __restrict__ ah_s, const float* __restrict__ ah_d, int n)
{
    __shared__ __half Ah[64 * AH_LD];
    __shared__ __half Bh[16 * BH_LD_H];
    __shared__ float Cs[64 * CS_LD_H];

    int tid = threadIdx.x, warp = tid >> 5;
    int warp_m = warp >> 1, warp_n = warp & 1;
    int row0 = blockIdx.x * 64;

    wmma::fragment<wmma::accumulator, 16, 16, 16, float> acc[2];
#pragma unroll
    for (int j = 0; j < 2; j++) wmma::fill_fragment(acc[j], 0.f);

    int a_row = tid >> 2;
    int a_kg = (tid & 3) * 4;
    int b_kk = tid >> 4;
    int b_col = (tid & 15) * 4;
    int grow = row0 + a_row;

    for (int k0 = 0; k0 < C; k0 += 16) {
        {
            uint2 raw = make_uint2(0u, 0u);
            if (grow < n) raw = *(const uint2*)(g_HR + (size_t)grow * C + k0 + a_kg);
            __half2* pa = (__half2*)(Ah + a_row * AH_LD + a_kg);
            pa[0] = *(__half2*)&raw.x;
            pa[1] = *(__half2*)&raw.y;
        }
        {
            float4 v = *(const float4*)(B1 + (size_t)(FIN + k0 + b_kk) * C + b_col);
            __half2* pb = (__half2*)(Bh + b_kk * BH_LD_H + b_col);
            pb[0] = __floats2half2_rn(v.x, v.y);
            pb[1] = __floats2half2_rn(v.z, v.w);
        }
        __syncthreads();

        wmma::fragment<wmma::matrix_a, 16, 16, 16, __half, wmma::row_major> fa;
        wmma::load_matrix_sync(fa, Ah + warp_m * 16 * AH_LD, AH_LD);
#pragma unroll
        for (int j = 0; j < 2; j++) {
            wmma::fragment<wmma::matrix_b, 16, 16, 16, __half, wmma::row_major> fb;
            wmma::load_matrix_sync(fb, Bh + warp_n * 32 + j * 16, BH_LD_H);
            wmma::mma_sync(acc[j], fa, fb, acc[j]);
        }
        __syncthreads();
    }

#pragma unroll
    for (int j = 0; j < 2; j++)
        wmma::store_matrix_sync(Cs + warp_m * 16 * CS_LD_H + warp_n * 32 + j * 16,
                                acc[j], CS_LD_H, wmma::mem_row_major);
    __syncthreads();
    {
        int r = tid >> 2, c0 = (tid & 3) * 16;
        int grow2 = row0 + r;
        float s = 0.f, d = 0.f;
#pragma unroll
        for (int c = 0; c < 16; c += 8) {
            float4 f0 = *(const float4*)(Cs + r * CS_LD_H + c0 + c);
            float4 f1 = *(const float4*)(Cs + r * CS_LD_H + c0 + c + 4);
            float4 p0 = make_float4(0.f, 0.f, 0.f, 0.f), p1 = p0;
            if (grow2 < n) {
                p0 = *(const float4*)(g_hhp + (size_t)grow2 * C + c0 + c);
                p1 = *(const float4*)(g_hhp + (size_t)grow2 * C + c0 + c + 4);
            }
            float v0 = f0.x + p0.x, v1 = f0.y + p0.y, v2 = f0.z + p0.z, v3 = f0.w + p0.w;
            float v4 = f1.x + p1.x, v5 = f1.y + p1.y, v6 = f1.z + p1.z, v7 = f1.w + p1.w;
            int cc = c0 + c;
            s += v0 * __ldg(ah_s + cc) + v1 * __ldg(ah_s + cc + 1)
               + v2 * __ldg(ah_s + cc + 2) + v3 * __ldg(ah_s + cc + 3)
               + v4 * __ldg(ah_s + cc + 4) + v5 * __ldg(ah_s + cc + 5)
               + v6 * __ldg(ah_s + cc + 6) + v7 * __ldg(ah_s + cc + 7);
            d += v0 * __ldg(ah_d + cc) + v1 * __ldg(ah_d + cc + 1)
               + v2 * __ldg(ah_d + cc + 2) + v3 * __ldg(ah_d + cc + 3)
               + v4 * __ldg(ah_d + cc + 4) + v5 * __ldg(ah_d + cc + 5)
               + v6 * __ldg(ah_d + cc + 6) + v7 * __ldg(ah_d + cc + 7);
            if (grow2 < n) {
                __half2 h0 = __floats2half2_rn(v0, v1);
                __half2 h1 = __floats2half2_rn(v2, v3);
                __half2 h2 = __floats2half2_rn(v4, v5);
                __half2 h3 = __floats2half2_rn(v6, v7);
                uint4 pk;
                pk.x = *(uint32_t*)&h0; pk.y = *(uint32_t*)&h1;
                pk.z = *(uint32_t*)&h2; pk.w = *(uint32_t*)&h3;
                *(uint4*)(g_hh + (size_t)grow2 * C + cc) = pk;
            }
        }
        s += __shfl_xor_sync(0xffffffffu, s, 1);
        s += __shfl_xor_sync(0xffffffffu, s, 2);
        d += __shfl_xor_sync(0xffffffffu, d, 1);
        d += __shfl_xor_sync(0xffffffffu, d, 2);
        if ((tid & 3) == 0 && grow2 < n) { g_als_h[grow2] = s; g_ald_h[grow2] = d; }
    }
}

// ================= fused per-dst accumulation (unroll-4) =====================
__global__ void zr_node(const float* __restrict__ H,
                        const float* __restrict__ bz, const float* __restrict__ br, int n)
{
    int d = (blockIdx.x * blockDim.x + threadIdx.x) >> 5;
    if (d >= n) return;
    int l = threadIdx.x & 31;

    float ez = 0.f, er = 0.f;
    if (l == 0)  ez = __expf(lrelu(g_als_z[d] + g_ald_z[d]));
    if (l == 16) er = __expf(lrelu(g_als_r[d] + g_ald_r[d]));
    ez = __shfl_sync(0xffffffffu, ez, 0);
    er = __shfl_sync(0xffffffffu, er, 16);

    uint2 raw = *(const uint2*)(g_hzr + (size_t)d * 128 + 4 * l);
    float2 vz = __half22float2(*(__half2*)&raw.x);
    float2 vr = __half22float2(*(__half2*)&raw.y);
    float az0 = vz.x * ez, az1 = vz.y * ez;
    float ar0 = vr.x * er, ar1 = vr.y * er;
    float denz = ez, denr = er;

    int b = g_rs[d], e_end = g_rs[d + 1];
    int i = b;
    for (; i + 3 < e_end; i += 4) {
        int s0 = g_csrc[i], s1 = g_csrc[i + 1], s2 = g_csrc[i + 2], s3 = g_csrc[i + 3];
        uint32_t w0 = g_ewzr[i], w1 = g_ewzr[i + 1], w2 = g_ewzr[i + 2], w3 = g_ewzr[i + 3];
        uint2 r0 = *(const uint2*)(g_hzr + (size_t)s0 * 128 + 4 * l);
        uint2 r1 = *(const uint2*)(g_hzr + (size_t)s1 * 128 + 4 * l);
        uint2 r2 = *(const uint2*)(g_hzr + (size_t)s2 * 128 + 4 * l);
        uint2 r3 = *(const uint2*)(g_hzr + (size_t)s3 * 128 + 4 * l);
        float2 e0 = __half22float2(*(__half2*)&w0);
        float2 e1 = __half22float2(*(__half2*)&w1);
        float2 e2 = __half22float2(*(__half2*)&w2);
        float2 e3 = __half22float2(*(__half2*)&w3);
        float2 uz0 = __half22float2(*(__half2*)&r0.x), ur0 = __half22float2(*(__half2*)&r0.y);
        float2 uz1 = __half22float2(*(__half2*)&r1.x), ur1 = __half22float2(*(__half2*)&r1.y);
        float2 uz2 = __half22float2(*(__half2*)&r2.x), ur2 = __half22float2(*(__half2*)&r2.y);
        float2 uz3 = __half22float2(*(__half2*)&r3.x), ur3 = __half22float2(*(__half2*)&r3.y);
        az0 += uz0.x * e0.x + uz1.x * e1.x + uz2.x * e2.x + uz3.x * e3.x;
        az1 += uz0.y * e0.x + uz1.y * e1.x + uz2.y * e2.x + uz3.y * e3.x;
        ar0 += ur0.x * e0.y + ur1.x * e1.y + ur2.x * e2.y + ur3.x * e3.y;
        ar1 += ur0.y * e0.y + ur1.y * e1.y + ur2.y * e2.y + ur3.y * e3.y;
        denz += e0.x + e1.x + e2.x + e3.x;
        denr += e0.y + e1.y + e2.y + e3.y;
    }
    for (; i < e_end; i++) {
        int s0 = g_csrc[i];
        uint32_t w0 = g_ewzr[i];
        float2 e0 = __half22float2(*(__half2*)&w0);
        uint2 r0 = *(const uint2*)(g_hzr + (size_t)s0 * 128 + 4 * l);
        float2 uz0 = __half22float2(*(__half2*)&r0.x);
        float2 ur0 = __half22float2(*(__half2*)&r0.y);
        az0 += uz0.x * e0.x; az1 += uz0.y * e0.x;
        ar0 += ur0.x * e0.y; ar1 += ur0.y * e0.y;
        denz += e0.x; denr += e0.y;
    }

    float iz = 1.f / (denz + 1e-16f), ir = 1.f / (denr + 1e-16f);
    float Z0 = sigmoidf_(az0 * iz + __ldg(bz + 2 * l));
    float Z1 = sigmoidf_(az1 * iz + __ldg(bz + 2 * l + 1));
    float R0 = sigmoidf_(ar0 * ir + __ldg(br + 2 * l));
    float R1 = sigmoidf_(ar1 * ir + __ldg(br + 2 * l + 1));
    float2 Hv = *(const float2*)(H + (size_t)d * C + 2 * l);
    *(float2*)(g_Z + (size_t)d * C + 2 * l) = make_float2(Z0, Z1);
    __half2 hr = __floats2half2_rn(Hv.x * R0, Hv.y * R1);
    *(uint32_t*)(g_HR + (size_t)d * C + 2 * l) = *(uint32_t*)&hr;
}

__global__ void h_node(const float* __restrict__ H, const float* __restrict__ bh,
                       float* __restrict__ out, int n)
{
    int d = (blockIdx.x * blockDim.x + threadIdx.x) >> 5;
    if (d >= n) return;
    int l = threadIdx.x & 31;

    float eh = 0.f;
    if (l == 0) eh = __expf(lrelu(g_als_h[d] + g_ald_h[d]));
    eh = __shfl_sync(0xffffffffu, eh, 0);

    uint32_t raw = *(const uint32_t*)(g_hh + (size_t)d * C + 2 * l);
    float2 v = __half22float2(*(__half2*)&raw);
    float a0 = v.x * eh, a1 = v.y * eh;
    float den = eh;

    int b = g_rs[d], e_end = g_rs[d + 1];
    int i = b;
    for (; i + 3 < e_end; i += 4) {
        int s0 = g_csrc[i], s1 = g_csrc[i + 1], s2 = g_csrc[i + 2], s3 = g_csrc[i + 3];
        float eh0 = __half2float(g_ewh[i]);
        float eh1 = __half2float(g_ewh[i + 1]);
        float eh2 = __half2float(g_ewh[i + 2]);
        float eh3 = __half2float(g_ewh[i + 3]);
        uint32_t w0 = *(const uint32_t*)(g_hh + (size_t)s0 * C + 2 * l);
        uint32_t w1 = *(const uint32_t*)(g_hh + (size_t)s1 * C + 2 * l);
        uint32_t w2 = *(const uint32_t*)(g_hh + (size_t)s2 * C + 2 * l);
        uint32_t w3 = *(const uint32_t*)(g_hh + (size_t)s3 * C + 2 * l);
        float2 u0 = __half22float2(*(__half2*)&w0);
        float2 u1 = __half22float2(*(__half2*)&w1);
        float2 u2 = __half22float2(*(__half2*)&w2);
        float2 u3 = __half22float2(*(__half2*)&w3);
        a0 += u0.x * eh0 + u1.x * eh1 + u2.x * eh2 + u3.x * eh3;
        a1 += u0.y * eh0 + u1.y * eh1 + u2.y * eh2 + u3.y * eh3;
        den += eh0 + eh1 + eh2 + eh3;
    }
    for (; i < e_end; i++) {
        int s0 = g_csrc[i];
        float eh0 = __half2float(g_ewh[i]);
        uint32_t w0 = *(const uint32_t*)(g_hh + (size_t)s0 * C + 2 * l);
        float2 u0 = __half22float2(*(__half2*)&w0);
        a0 += u0.x * eh0; a1 += u0.y * eh0;
        den += eh0;
    }

    float inv = 1.f / (den + 1e-16f);
    float ht0 = tanhf(a0 * inv + __ldg(bh + 2 * l));
    float ht1 = tanhf(a1 * inv + __ldg(bh + 2 * l + 1));
    float2 Zv = *(const float2*)(g_Z + (size_t)d * C + 2 * l);
    float2 Hv = *(const float2*)(H + (size_t)d * C + 2 * l);
    float o0 = Zv.x * Hv.x + (1.f - Zv.x) * ht0;
    float o1 = Zv.y * Hv.y + (1.f - Zv.y) * ht1;
    *(float2*)(out + (size_t)d * C + 2 * l) = make_float2(o0, o1);
}

// ---------------- launch ----------------
extern "C" void kernel_launch(void* const* d_in, const int* in_sizes, int n_in,
                              void* d_out, int out_size)
{
    const float* X    = (const float*)d_in[0];
    const int*   ei   = (const int*)  d_in[1];
    const float* H    = (const float*)d_in[2];
    const float* Wz   = (const float*)d_in[3];
    const float* az_s = (const float*)d_in[4];
    const float* az_d = (const float*)d_in[5];
    const float* bz   = (const float*)d_in[6];
    const float* Wr   = (const float*)d_in[7];
    const float* ar_s = (const float*)d_in[8];
    const float* ar_d = (const float*)d_in[9];
    const float* br   = (const float*)d_in[10];
    const float* Wh   = (const float*)d_in[11];
    const float* ah_s = (const float*)d_in[12];
    const float* ah_d = (const float*)d_in[13];
    const float* bh   = (const float*)d_in[14];

    int n = in_sizes[0] / FIN;
    int E = in_sizes[1] / 2;
    const int* src = ei;
    const int* dst = ei + E;

    int nb = (n + SCAN_B - 1) / SCAN_B;
    int gemm_blocks = (n + 63) / 64;
    int warp_blocks = (n * 32 + 255) / 256;
    int eth = (E + 255) / 256;

    static cudaStream_t s_side = nullptr;
    static cudaEvent_t s_fork = nullptr, s_csr = nullptr, s_hx = nullptr;
    if (s_side == nullptr) {
        cudaStreamCreateWithFlags(&s_side, cudaStreamNonBlocking);
        cudaEventCreateWithFlags(&s_fork, cudaEventDisableTiming);
        cudaEventCreateWithFlags(&s_csr, cudaEventDisableTiming);
        cudaEventCreateWithFlags(&s_hx, cudaEventDisableTiming);
    }

    cudaEventRecord(s_fork, 0);
    cudaStreamWaitEvent(s_side, s_fork, 0);

    k_zero_cnt<<<(n + 255) / 256, 256, 0, s_side>>>(n);       // 0 (side)
    k_count<<<eth, 256, 0, s_side>>>(dst, E);                 // 1 (side)
    k_scan1<<<nb, SCAN_B, 0, s_side>>>(n);                    // 2 (side)
    gemm_zr<<<gemm_blocks, 256>>>(X, H, Wz, Wr,
                                  az_s, az_d, ar_s, ar_d, n); // 3 (main) <- profiled
    k_scan2<<<1, 512, 0, s_side>>>(nb, n);                    // 4 (side)
    k_scan3<<<nb, SCAN_B, 0, s_side>>>(n);                    // 5 (side)
    k_scatter<<<eth, 256, 0, s_side>>>(src, dst, E);          // 6 (side)
    cudaEventRecord(s_csr, s_side);
    gemm_hx<<<gemm_blocks, 256, 0, s_side>>>(X, Wh, n);       // 7 (side)
    cudaEventRecord(s_hx, s_side);

    cudaStreamWaitEvent(0, s_csr, 0);                         // need CSR + als_zr
    ew_zr<<<eth, 256>>>(E);
    zr_node<<<warp_blocks, 256>>>(H, bz, br, n);

    cudaStreamWaitEvent(0, s_hx, 0);                          // need X@Wh partial
    gemm_hhr<<<gemm_blocks, 256>>>(Wh, ah_s, ah_d, n);
    ew_h<<<eth, 256>>>(E);
    h_node<<<warp_blocks, 256>>>(H, bh, (float*)d_out, n);
}